// round 9
// baseline (speedup 1.0000x reference)
#include <cuda_runtime.h>

#define Bsz 32
#define Tenc 400
#define Hd 512
#define Lsteps 100
#define Vout 511
#define KS 15
#define NBLK 128
#define GBLK 32     // blocks per group (one group = 8 batch elems)

// ---------------- persistent state ------------------------------------------
__device__ float g_hx[2][Bsz * Hd];
__device__ float g_ctxp[4][Bsz * Hd];   // per-t-tile partial contexts (x inv)
__device__ float g_scores[Bsz * Tenc];
__device__ unsigned g_bars[4];          // per-group barrier counters

__device__ __forceinline__ float warp_sum(float v) {
    #pragma unroll
    for (int o = 16; o; o >>= 1) v += __shfl_xor_sync(0xffffffffu, v, o);
    return v;
}
__device__ __forceinline__ float warp_max(float v) {
    #pragma unroll
    for (int o = 16; o; o >>= 1) v = fmaxf(v, __shfl_xor_sync(0xffffffffu, v, o));
    return v;
}

// ---- f32x2 packed math ------------------------------------------------------
typedef unsigned long long u64;
__device__ __forceinline__ u64 pack2(float lo, float hi) {
    u64 r;
    asm("mov.b64 %0, {%1, %2};" : "=l"(r) : "f"(lo), "f"(hi));
    return r;
}
__device__ __forceinline__ void unpack2(u64 v, float& lo, float& hi) {
    asm("mov.b64 {%0, %1}, %2;" : "=f"(lo), "=f"(hi) : "l"(v));
}
__device__ __forceinline__ void fma2(u64& d, u64 a, u64 b) {
    asm("fma.rn.f32x2 %0, %1, %2, %0;" : "+l"(d) : "l"(a), "l"(b));
}

__global__ void bar_init() {
    g_bars[0] = 0u; g_bars[1] = 0u; g_bars[2] = 0u; g_bars[3] = 0u;
}

struct __align__(16) SmemT {
    union {
        struct { float ix[8][Hd]; float hx[8][Hd]; float fin[8][Hd]; } p1; // 48KB
        struct { float win[128]; float part[16][100]; } p2;
        struct { float a[Tenc]; float red[16]; } p3;
    };
};

__global__ void __launch_bounds__(512, 1) seq2seq_persist(
    const float* __restrict__ x, const int* __restrict__ y,
    const float* __restrict__ emb,
    const float* __restrict__ W_ih, const float* __restrict__ W_hh,
    const float* __restrict__ b_ih, const float* __restrict__ b_hh,
    const float* __restrict__ conv_w, const float* __restrict__ conv_b,
    const float* __restrict__ attn_w, const float* __restrict__ attn_b,
    const float* __restrict__ fc_w, const float* __restrict__ fc_b,
    float* __restrict__ out, float* __restrict__ aligns)
{
    __shared__ SmemT sm;
    const int bid  = blockIdx.x;
    const int grp  = bid >> 5;          // 0..3 — batch octet
    const int lblk = bid & 31;          // 0..31 within group
    const int b0   = grp << 3;
    const int tid  = threadIdx.x;
    const int w = tid >> 5, lane = tid & 31;

    unsigned barn = 0;

    #define GRID_BARRIER() do {                                              \
        barn++;                                                              \
        __syncthreads();                                                     \
        if (tid == 0) {                                                      \
            __threadfence();                                                 \
            atomicAdd(&g_bars[grp], 1u);                                     \
            unsigned target = barn * GBLK;                                   \
            while ((int)(*((volatile unsigned*)&g_bars[grp]) - target) < 0)  \
                __nanosleep(32);                                             \
        }                                                                    \
        __syncthreads();                                                     \
    } while (0)

    for (int t = 0; t < Lsteps; t++) {
        const int rd = t & 1, wr = rd ^ 1;

        // ===== phase 1: GRU + fc(t-1). block = 16 h-rows (ht=lblk) x 8 b ====
        {
            const int ht = lblk;
            const int h0 = ht << 4;

            // --- stage activations (float4) ---
            for (int idx = tid; idx < 8 * (Hd / 4); idx += 512) {
                int bb = idx >> 7, i4 = idx & 127;
                int b = b0 + bb;
                int tok = y[b * 101 + t];
                float4 sx4 = make_float4(0.f, 0.f, 0.f, 0.f);
                float4 hx4 = make_float4(0.f, 0.f, 0.f, 0.f);
                if (t > 0) {
                    float4 c0 = __ldcg((const float4*)&g_ctxp[0][b * Hd] + i4);
                    float4 c1 = __ldcg((const float4*)&g_ctxp[1][b * Hd] + i4);
                    float4 c2 = __ldcg((const float4*)&g_ctxp[2][b * Hd] + i4);
                    float4 c3 = __ldcg((const float4*)&g_ctxp[3][b * Hd] + i4);
                    sx4.x = (c0.x + c1.x) + (c2.x + c3.x);
                    sx4.y = (c0.y + c1.y) + (c2.y + c3.y);
                    sx4.z = (c0.z + c1.z) + (c2.z + c3.z);
                    sx4.w = (c0.w + c1.w) + (c2.w + c3.w);
                    hx4 = __ldcg((const float4*)&g_hx[rd][b * Hd] + i4);
                }
                float4 e = ((const float4*)emb)[(size_t)tok * (Hd / 4) + i4];
                ((float4*)sm.p1.ix)[bb * 128 + i4] =
                    make_float4(e.x + sx4.x, e.y + sx4.y, e.z + sx4.z, e.w + sx4.w);
                ((float4*)sm.p1.hx)[bb * 128 + i4] = hx4;
                ((float4*)sm.p1.fin)[bb * 128 + i4] =
                    make_float4(hx4.x + sx4.x, hx4.y + sx4.y, hx4.z + sx4.z, hx4.w + sx4.w);
            }
            __syncthreads();

            // --- warp roles: 0-5 W_ih rows, 6-11 W_hh rows, 12-13 fc rows ---
            float acc[8][8];
            bool is_mm = (w < 12);
            bool is_fc = (w >= 12 && w < 14);

            if (is_mm) {
                int wl = (w < 6) ? w : (w - 6);
                int gate = wl >> 1, s = wl & 1;
                const float* Wb = (w < 6) ? W_ih : W_hh;
                const float* rows[8];
                #pragma unroll
                for (int r = 0; r < 8; r++)
                    rows[r] = Wb + (size_t)(gate * Hd + h0 + s * 8 + r) * Hd;
                const float (*act)[Hd] = (w < 6) ? sm.p1.ix : sm.p1.hx;

                #pragma unroll
                for (int r = 0; r < 8; r++)
                    #pragma unroll
                    for (int bb = 0; bb < 8; bb++) acc[r][bb] = 0.0f;

                for (int i = lane; i < Hd; i += 32) {
                    float a_[8];
                    #pragma unroll
                    for (int bb = 0; bb < 8; bb++) a_[bb] = act[bb][i];
                    #pragma unroll
                    for (int r = 0; r < 8; r++) {
                        float wv = rows[r][i];
                        #pragma unroll
                        for (int bb = 0; bb < 8; bb++)
                            acc[r][bb] = fmaf(wv, a_[bb], acc[r][bb]);
                    }
                }
                #pragma unroll
                for (int r = 0; r < 8; r++)
                    #pragma unroll
                    for (int bb = 0; bb < 8; bb++) acc[r][bb] = warp_sum(acc[r][bb]);
            } else if (is_fc && t > 0) {
                int vb = (ht << 4) + (w - 12) * 8;
                const float* rows[8];
                #pragma unroll
                for (int r = 0; r < 8; r++)
                    rows[r] = fc_w + (size_t)((vb + r < Vout) ? vb + r : 0) * Hd;

                #pragma unroll
                for (int r = 0; r < 8; r++)
                    #pragma unroll
                    for (int bb = 0; bb < 8; bb++) acc[r][bb] = 0.0f;

                for (int i = lane; i < Hd; i += 32) {
                    float a_[8];
                    #pragma unroll
                    for (int bb = 0; bb < 8; bb++) a_[bb] = sm.p1.fin[bb][i];
                    #pragma unroll
                    for (int r = 0; r < 8; r++) {
                        float wv = rows[r][i];
                        #pragma unroll
                        for (int bb = 0; bb < 8; bb++)
                            acc[r][bb] = fmaf(wv, a_[bb], acc[r][bb]);
                    }
                }
                #pragma unroll
                for (int r = 0; r < 8; r++)
                    #pragma unroll
                    for (int bb = 0; bb < 8; bb++) acc[r][bb] = warp_sum(acc[r][bb]);

                // fc rows write straight to out (no smem needed)
                #pragma unroll
                for (int r = 0; r < 8; r++)
                    #pragma unroll
                    for (int bb = 0; bb < 8; bb++)
                        if (lane == ((r * 8 + bb) & 31)) {
                            int v = vb + r;
                            if (v < Vout)
                                out[(size_t)(b0 + bb) * Lsteps * Vout +
                                    (size_t)(t - 1) * Vout + v] = acc[r][bb] + fc_b[v];
                        }
            }
            __syncthreads();   // all reads of ix/hx/fin done -> safe to overlay

            // --- route gate partials via smem (overlays ix area, 3KB) ---
            float* S = (float*)&sm;   // S[(w*8+r)*8+bb], rows 0..95
            if (is_mm) {
                #pragma unroll
                for (int r = 0; r < 8; r++)
                    #pragma unroll
                    for (int bb = 0; bb < 8; bb++)
                        if (lane == ((r * 8 + bb) & 31))
                            S[(w * 8 + r) * 8 + bb] = acc[r][bb];
            }
            __syncthreads();

            // --- GRU combine: 128 threads = 16 h x 8 b ---
            if (tid < 128) {
                int bbc = tid & 7, hl = tid >> 3;
                int h = h0 + hl, b = b0 + bbc;
                float ir = S[(0  + hl) * 8 + bbc];
                float iz = S[(16 + hl) * 8 + bbc];
                float in_ = S[(32 + hl) * 8 + bbc];
                float hr = S[(48 + hl) * 8 + bbc];
                float hz = S[(64 + hl) * 8 + bbc];
                float hn = S[(80 + hl) * 8 + bbc];
                float gr = ir + b_ih[h] + hr + b_hh[h];
                float gz = iz + b_ih[Hd + h] + hz + b_hh[Hd + h];
                float r = 1.0f / (1.0f + expf(-gr));
                float z = 1.0f / (1.0f + expf(-gz));
                float n = tanhf(in_ + b_ih[2 * Hd + h] + r * (hn + b_hh[2 * Hd + h]));
                float hp = sm.p1.hx[bbc][h];
                g_hx[wr][b * Hd + h] = (1.0f - z) * n + z * hp;
            }
        }
        GRID_BARRIER();

        // ===== phase 2: attention scores. block = (b, t-tile 100) ===========
        {
            int b = b0 + (lblk >> 2);
            int T0 = (lblk & 3) * 100;
            int h = (w << 5) + lane;

            if (tid < 114) {
                int j = T0 - 7 + tid;
                float vv = 0.0f;
                if (t > 0 && j >= 0 && j < Tenc)
                    vv = __ldcg(&aligns[(size_t)b * Lsteps * Tenc +
                                        (size_t)(t - 1) * Tenc + j]);
                sm.p2.win[tid] = vv;
            }

            float cw[KS];
            #pragma unroll
            for (int k = 0; k < KS; k++) cw[k] = conv_w[h * KS + k];
            u64 cwp[7];
            #pragma unroll
            for (int m = 0; m < 7; m++) cwp[m] = pack2(cw[2 * m], cw[2 * m + 1]);
            float cw14  = cw[14];
            float cbv   = conv_b[h];
            float attwv = attn_w[h];
            float hxv   = __ldcg(&g_hx[wr][b * Hd + h]);
            __syncthreads();

            const float* xb = x + (size_t)b * Tenc * Hd + h;

            if (t > 0) {
                #pragma unroll 1
                for (int tc = 0; tc < 10; tc++) {
                    int tl0 = tc * 10;
                    float xv[10];
                    #pragma unroll
                    for (int i = 0; i < 10; i++)
                        xv[i] = xb[(size_t)(T0 + tl0 + i) * Hd];
                    float wvr[24];
                    #pragma unroll
                    for (int j = 0; j < 24; j++) wvr[j] = sm.p2.win[tl0 + j];

                    {   // even i
                        u64 Pe[11];
                        #pragma unroll
                        for (int m = 0; m < 11; m++)
                            Pe[m] = pack2(wvr[2 * m], wvr[2 * m + 1]);
                        #pragma unroll
                        for (int i = 0; i < 10; i += 2) {
                            int j = i >> 1;
                            u64 a2 = pack2(cbv, 0.0f);
                            #pragma unroll
                            for (int m = 0; m < 7; m++) fma2(a2, cwp[m], Pe[j + m]);
                            float lo, hi; unpack2(a2, lo, hi);
                            float conv = lo + hi + cw14 * wvr[i + 14];
                            float p = xv[i] + hxv + conv;
                            float part = warp_sum(fmaxf(p, 0.0f) * attwv);
                            if (lane == 0) sm.p2.part[w][tl0 + i] = part;
                        }
                    }
                    {   // odd i
                        u64 Po[11];
                        #pragma unroll
                        for (int m = 0; m < 11; m++)
                            Po[m] = pack2(wvr[2 * m + 1], wvr[2 * m + 2]);
                        #pragma unroll
                        for (int i = 1; i < 10; i += 2) {
                            int j = (i - 1) >> 1;
                            u64 a2 = pack2(cbv, 0.0f);
                            #pragma unroll
                            for (int m = 0; m < 7; m++) fma2(a2, cwp[m], Po[j + m]);
                            float lo, hi; unpack2(a2, lo, hi);
                            float conv = lo + hi + cw14 * wvr[i + 14];
                            float p = xv[i] + hxv + conv;
                            float part = warp_sum(fmaxf(p, 0.0f) * attwv);
                            if (lane == 0) sm.p2.part[w][tl0 + i] = part;
                        }
                    }
                }
            } else {
                #pragma unroll 1
                for (int tc = 0; tc < 10; tc++) {
                    int tl0 = tc * 10;
                    float xv[10];
                    #pragma unroll
                    for (int i = 0; i < 10; i++)
                        xv[i] = xb[(size_t)(T0 + tl0 + i) * Hd];
                    #pragma unroll
                    for (int i = 0; i < 10; i++) {
                        float p = xv[i] + hxv;
                        float part = warp_sum(fmaxf(p, 0.0f) * attwv);
                        if (lane == 0) sm.p2.part[w][tl0 + i] = part;
                    }
                }
            }
            __syncthreads();
            if (tid < 100) {
                float s = 0.0f;
                #pragma unroll
                for (int c2 = 0; c2 < 16; c2++) s += sm.p2.part[c2][tid];
                g_scores[b * Tenc + T0 + tid] = s + attn_b[0];
            }
        }
        GRID_BARRIER();

        // ===== phase 3: softmax + PARTIAL context. block = (b, t-tile 100) ===
        {
            int b = b0 + (lblk >> 2);
            int tile = lblk & 3;
            int T0 = tile * 100;

            float sv = (tid < Tenc) ? __ldcg(&g_scores[b * Tenc + tid]) : -1e30f;
            float m = warp_max(sv);
            if (lane == 0) sm.p3.red[w] = m;
            __syncthreads();
            float bm = -1e30f;
            #pragma unroll
            for (int j = 0; j < 16; j++) bm = fmaxf(bm, sm.p3.red[j]);

            float e = (tid < Tenc) ? __expf(sv - bm) : 0.0f;
            if (tid < Tenc) sm.p3.a[tid] = e;
            float sum = warp_sum(e);
            __syncthreads();
            if (lane == 0) sm.p3.red[w] = sum;
            __syncthreads();
            float tot = 0.0f;
            #pragma unroll
            for (int j = 0; j < 16; j++) tot += sm.p3.red[j];
            float inv = 1.0f / tot;

            const float* xb = x + (size_t)b * Tenc * Hd + (size_t)T0 * Hd + tid;
            float acc[5];
            #pragma unroll
            for (int j = 0; j < 5; j++) acc[j] = 0.0f;
            #pragma unroll 1
            for (int c = 0; c < 10; c++) {
                int i0 = c * 10;
                float xr[10];
                #pragma unroll
                for (int i = 0; i < 10; i++)
                    xr[i] = xb[(size_t)(i0 + i) * Hd];
                #pragma unroll
                for (int i = 0; i < 10; i++)
                    acc[i % 5] = fmaf(sm.p3.a[T0 + i0 + i], xr[i], acc[i % 5]);
            }
            float r = (acc[0] + acc[1]) + (acc[2] + acc[3]) + acc[4];
            g_ctxp[tile][b * Hd + tid] = r * inv;

            if (tid < 100)
                aligns[(size_t)b * Lsteps * Tenc + (size_t)t * Tenc + T0 + tid] =
                    sm.p3.a[T0 + tid] * inv;
        }
        GRID_BARRIER();
    }

    // ===== final fc for step 99 (hx in buffer 0) ============================
    {
        const int vt = lblk;
        const int v = (vt << 4) + w;

        for (int idx = tid; idx < 8 * Hd; idx += 512) {
            int bb = idx >> 9, i = idx & 511;
            int b = b0 + bb;
            float sxv = __ldcg(&g_ctxp[0][b * Hd + i]) +
                        __ldcg(&g_ctxp[1][b * Hd + i]) +
                        __ldcg(&g_ctxp[2][b * Hd + i]) +
                        __ldcg(&g_ctxp[3][b * Hd + i]);
            sm.p1.fin[bb][i] = __ldcg(&g_hx[0][b * Hd + i]) + sxv;
        }
        __syncthreads();

        if (v < Vout) {
            const float* fw = fc_w + (size_t)v * Hd;
            float fac[8];
            #pragma unroll
            for (int bb = 0; bb < 8; bb++) fac[bb] = 0.0f;
            for (int i = lane; i < Hd; i += 32) {
                float wv = fw[i];
                #pragma unroll
                for (int bb = 0; bb < 8; bb++)
                    fac[bb] = fmaf(wv, sm.p1.fin[bb][i], fac[bb]);
            }
            #pragma unroll
            for (int bb = 0; bb < 8; bb++) fac[bb] = warp_sum(fac[bb]);
            if (lane < 8) {
                int b = b0 + lane;
                out[(size_t)b * Lsteps * Vout + (size_t)(Lsteps - 1) * Vout + v] =
                    fac[lane] + fc_b[v];
            }
        }
    }
    #undef GRID_BARRIER
}

// ---------------- launch ------------------------------------------------------
extern "C" void kernel_launch(void* const* d_in, const int* in_sizes, int n_in,
                              void* d_out, int out_size)
{
    const float* x      = (const float*)d_in[0];
    const int*   y      = (const int*)  d_in[1];
    const float* emb    = (const float*)d_in[2];
    const float* W_ih   = (const float*)d_in[3];
    const float* W_hh   = (const float*)d_in[4];
    const float* b_ih   = (const float*)d_in[5];
    const float* b_hh   = (const float*)d_in[6];
    const float* conv_w = (const float*)d_in[7];
    const float* conv_b = (const float*)d_in[8];
    const float* attn_w = (const float*)d_in[9];
    const float* attn_b = (const float*)d_in[10];
    const float* fc_w   = (const float*)d_in[11];
    const float* fc_b   = (const float*)d_in[12];

    float* out    = (float*)d_out;
    float* aligns = out + (size_t)Bsz * Lsteps * Vout;

    bar_init<<<1, 1>>>();
    seq2seq_persist<<<NBLK, 512>>>(x, y, emb, W_ih, W_hh, b_ih, b_hh,
                                   conv_w, conv_b, attn_w, attn_b,
                                   fc_w, fc_b, out, aligns);
}

// round 10
// speedup vs baseline: 1.2553x; 1.2553x over previous
#include <cuda_runtime.h>

#define Bsz 32
#define Tenc 400
#define Hd 512
#define Lsteps 100
#define Vout 511
#define KS 15
#define NBLK 128

// ---------------- persistent state ------------------------------------------
__device__ float g_hx[2][Bsz * Hd];
__device__ float g_ctxp[4][Bsz * Hd];   // per-t-tile partial contexts (x inv)
__device__ float g_scores[Bsz * Tenc];
__device__ unsigned g_bar;              // zeroed by bar_init each launch

__device__ __forceinline__ float warp_sum(float v) {
    #pragma unroll
    for (int o = 16; o; o >>= 1) v += __shfl_xor_sync(0xffffffffu, v, o);
    return v;
}
__device__ __forceinline__ float warp_max(float v) {
    #pragma unroll
    for (int o = 16; o; o >>= 1) v = fmaxf(v, __shfl_xor_sync(0xffffffffu, v, o));
    return v;
}

// ---- f32x2 packed math ------------------------------------------------------
typedef unsigned long long u64;
__device__ __forceinline__ u64 pack2(float lo, float hi) {
    u64 r;
    asm("mov.b64 %0, {%1, %2};" : "=l"(r) : "f"(lo), "f"(hi));
    return r;
}
__device__ __forceinline__ void unpack2(u64 v, float& lo, float& hi) {
    asm("mov.b64 {%0, %1}, %2;" : "=f"(lo), "=f"(hi) : "l"(v));
}
__device__ __forceinline__ void fma2(u64& d, u64 a, u64 b) {
    asm("fma.rn.f32x2 %0, %1, %2, %0;" : "+l"(d) : "l"(a), "l"(b));
}

__global__ void bar_init() { g_bar = 0u; }

struct __align__(16) SmemT {
    union {
        struct { float2 ix[4][Hd]; float2 hx[4][Hd]; float2 fin[4][Hd]; } p1; // 48KB
        struct { float in[8][Hd]; } pf;                                        // 16KB
        struct { float win[128]; float part[8][100]; } p2;
        struct { float a[Tenc]; float red[16]; } p3;
    };
};

__global__ void __launch_bounds__(512, 1) seq2seq_persist(
    const float* __restrict__ x, const int* __restrict__ y,
    const float* __restrict__ emb,
    const float* __restrict__ W_ih, const float* __restrict__ W_hh,
    const float* __restrict__ b_ih, const float* __restrict__ b_hh,
    const float* __restrict__ conv_w, const float* __restrict__ conv_b,
    const float* __restrict__ attn_w, const float* __restrict__ attn_b,
    const float* __restrict__ fc_w, const float* __restrict__ fc_b,
    float* __restrict__ out, float* __restrict__ aligns)
{
    __shared__ SmemT sm;
    const int bid = blockIdx.x;
    const int tid = threadIdx.x;
    const int w = tid >> 5, lane = tid & 31;

    unsigned barn = 0;

    #define GRID_BARRIER() do {                                              \
        barn++;                                                              \
        __syncthreads();                                                     \
        if (tid == 0) {                                                      \
            __threadfence();                                                 \
            atomicAdd(&g_bar, 1u);                                           \
            unsigned target = barn * NBLK;                                   \
            while ((int)(*((volatile unsigned*)&g_bar) - target) < 0)        \
                __nanosleep(32);                                             \
        }                                                                    \
        __syncthreads();                                                     \
    } while (0)

    for (int t = 0; t < Lsteps; t++) {
        const int rd = t & 1, wr = rd ^ 1;

        // ===== phase 1: GRU + fc(t-1). block = (ht 16h, bt 8b); warp=(1h,8b)
        // activations stored as b-pairs (float2) for f32x2 math
        {
            const int bt = bid & 3, ht = bid >> 2;
            const int b0 = bt << 3;
            const int h = (ht << 4) + w;     // GRU output row == fc row

            for (int idx = tid; idx < 8 * (Hd / 4); idx += 512) {
                int bb = idx >> 7, i4 = (idx & 127) << 2;
                int b = b0 + bb;
                int tok = y[b * 101 + t];
                float4 sx4 = make_float4(0.f, 0.f, 0.f, 0.f);
                float4 hx4 = make_float4(0.f, 0.f, 0.f, 0.f);
                if (t > 0) {
                    float4 c0 = __ldcg((const float4*)&g_ctxp[0][b * Hd] + (i4 >> 2));
                    float4 c1 = __ldcg((const float4*)&g_ctxp[1][b * Hd] + (i4 >> 2));
                    float4 c2 = __ldcg((const float4*)&g_ctxp[2][b * Hd] + (i4 >> 2));
                    float4 c3 = __ldcg((const float4*)&g_ctxp[3][b * Hd] + (i4 >> 2));
                    sx4.x = (c0.x + c1.x) + (c2.x + c3.x);
                    sx4.y = (c0.y + c1.y) + (c2.y + c3.y);
                    sx4.z = (c0.z + c1.z) + (c2.z + c3.z);
                    sx4.w = (c0.w + c1.w) + (c2.w + c3.w);
                    hx4 = __ldcg((const float4*)&g_hx[rd][b * Hd] + (i4 >> 2));
                }
                float4 e = ((const float4*)emb)[(size_t)tok * (Hd / 4) + (i4 >> 2)];
                int p = bb >> 1, off = bb & 1;
                float* dix = (float*)&sm.p1.ix[p][i4] + off;
                float* dhx = (float*)&sm.p1.hx[p][i4] + off;
                float* dfn = (float*)&sm.p1.fin[p][i4] + off;
                dix[0] = e.x + sx4.x; dix[2] = e.y + sx4.y;
                dix[4] = e.z + sx4.z; dix[6] = e.w + sx4.w;
                dhx[0] = hx4.x; dhx[2] = hx4.y; dhx[4] = hx4.z; dhx[6] = hx4.w;
                dfn[0] = hx4.x + sx4.x; dfn[2] = hx4.y + sx4.y;
                dfn[4] = hx4.z + sx4.z; dfn[6] = hx4.w + sx4.w;
            }
            __syncthreads();

            const float* wi0 = W_ih + (size_t)h * Hd;
            const float* wi1 = W_ih + (size_t)(Hd + h) * Hd;
            const float* wi2 = W_ih + (size_t)(2 * Hd + h) * Hd;
            const float* wh0 = W_hh + (size_t)h * Hd;
            const float* wh1 = W_hh + (size_t)(Hd + h) * Hd;
            const float* wh2 = W_hh + (size_t)(2 * Hd + h) * Hd;
            const float* fw  = fc_w + (size_t)(h < Vout ? h : 0) * Hd;

            u64 acc2[6][4], fac2[4];
            #pragma unroll
            for (int g = 0; g < 6; g++)
                #pragma unroll
                for (int j = 0; j < 4; j++) acc2[g][j] = pack2(0.f, 0.f);
            #pragma unroll
            for (int j = 0; j < 4; j++) fac2[j] = pack2(0.f, 0.f);

            const u64* six = (const u64*)sm.p1.ix;
            const u64* shx = (const u64*)sm.p1.hx;
            const u64* sfn = (const u64*)sm.p1.fin;

            for (int i = lane; i < Hd; i += 32) {
                u64 W0 = pack2(wi0[i], wi0[i]);
                u64 W1 = pack2(wi1[i], wi1[i]);
                u64 W2 = pack2(wi2[i], wi2[i]);
                u64 W3 = pack2(wh0[i], wh0[i]);
                u64 W4 = pack2(wh1[i], wh1[i]);
                u64 W5 = pack2(wh2[i], wh2[i]);
                u64 W6 = pack2(fw[i],  fw[i]);
                #pragma unroll
                for (int j = 0; j < 4; j++) {
                    u64 xi = six[j * Hd + i];
                    u64 xh = shx[j * Hd + i];
                    u64 xf = sfn[j * Hd + i];
                    fma2(acc2[0][j], W0, xi);
                    fma2(acc2[1][j], W1, xi);
                    fma2(acc2[2][j], W2, xi);
                    fma2(acc2[3][j], W3, xh);
                    fma2(acc2[4][j], W4, xh);
                    fma2(acc2[5][j], W5, xh);
                    fma2(fac2[j],    W6, xf);
                }
            }

            float accs[6][8], facs[8];
            #pragma unroll
            for (int g = 0; g < 6; g++)
                #pragma unroll
                for (int j = 0; j < 4; j++)
                    unpack2(acc2[g][j], accs[g][2 * j], accs[g][2 * j + 1]);
            #pragma unroll
            for (int j = 0; j < 4; j++)
                unpack2(fac2[j], facs[2 * j], facs[2 * j + 1]);

            #pragma unroll
            for (int g = 0; g < 6; g++)
                #pragma unroll
                for (int bb = 0; bb < 8; bb++) accs[g][bb] = warp_sum(accs[g][bb]);
            #pragma unroll
            for (int bb = 0; bb < 8; bb++) facs[bb] = warp_sum(facs[bb]);

            if (lane < 8) {
                int bb = lane, b = b0 + bb;
                float gr = accs[0][bb] + b_ih[h] + accs[3][bb] + b_hh[h];
                float gz = accs[1][bb] + b_ih[Hd + h] + accs[4][bb] + b_hh[Hd + h];
                float r = 1.0f / (1.0f + expf(-gr));
                float z = 1.0f / (1.0f + expf(-gz));
                float n = tanhf(accs[2][bb] + b_ih[2 * Hd + h] +
                                r * (accs[5][bb] + b_hh[2 * Hd + h]));
                float2 hv = sm.p1.hx[bb >> 1][h];
                float hp = (bb & 1) ? hv.y : hv.x;
                g_hx[wr][b * Hd + h] = (1.0f - z) * n + z * hp;
                if (t > 0 && h < Vout)
                    out[(size_t)b * Lsteps * Vout + (size_t)(t - 1) * Vout + h] =
                        facs[bb] + fc_b[h];
            }
        }
        GRID_BARRIER();

        // ===== phase 2: scores. block=(b, 100t). warp=(t-half 50, 64 h) =====
        {
            int b = bid >> 2;
            int T0 = (bid & 3) * 100;
            int tw = w & 7, thalf = w >> 3;
            int h0 = tw * 64 + lane * 2;          // this thread: h0, h0+1

            if (tid < 114) {
                int j = T0 - 7 + tid;
                float vv = 0.0f;
                if (t > 0 && j >= 0 && j < Tenc)
                    vv = __ldcg(&aligns[(size_t)b * Lsteps * Tenc +
                                        (size_t)(t - 1) * Tenc + j]);
                sm.p2.win[tid] = vv;
            }

            u64 cwp0[7], cwp1[7];
            float cw14_0, cw14_1;
            {
                const float* c0p = conv_w + h0 * KS;
                const float* c1p = conv_w + (h0 + 1) * KS;
                #pragma unroll
                for (int m = 0; m < 7; m++) {
                    cwp0[m] = pack2(c0p[2 * m], c0p[2 * m + 1]);
                    cwp1[m] = pack2(c1p[2 * m], c1p[2 * m + 1]);
                }
                cw14_0 = c0p[14]; cw14_1 = c1p[14];
            }
            float cb0 = conv_b[h0],  cb1 = conv_b[h0 + 1];
            float aw0 = attn_w[h0],  aw1 = attn_w[h0 + 1];
            float2 hx2 = __ldcg((const float2*)&g_hx[wr][b * Hd + h0]);
            __syncthreads();

            const float2* xb2 = (const float2*)(x + (size_t)b * Tenc * Hd) + (h0 >> 1);
            const int tbase = thalf * 50;

            if (t > 0) {
                #pragma unroll 1
                for (int tc = 0; tc < 5; tc++) {
                    int tl0 = tbase + tc * 10;
                    float2 xv[10];
                    #pragma unroll
                    for (int i = 0; i < 10; i++)
                        xv[i] = xb2[(size_t)(T0 + tl0 + i) * (Hd / 2)];
                    float wvr[24];
                    #pragma unroll
                    for (int j = 0; j < 24; j++) wvr[j] = sm.p2.win[tl0 + j];

                    {   // even i
                        u64 Pe[11];
                        #pragma unroll
                        for (int m = 0; m < 11; m++)
                            Pe[m] = pack2(wvr[2 * m], wvr[2 * m + 1]);
                        #pragma unroll
                        for (int i = 0; i < 10; i += 2) {
                            int j = i >> 1;
                            u64 a0 = pack2(cb0, 0.0f), a1 = pack2(cb1, 0.0f);
                            #pragma unroll
                            for (int m = 0; m < 7; m++) {
                                fma2(a0, cwp0[m], Pe[j + m]);
                                fma2(a1, cwp1[m], Pe[j + m]);
                            }
                            float l0, hh0, l1, hh1;
                            unpack2(a0, l0, hh0); unpack2(a1, l1, hh1);
                            float conv0 = l0 + hh0 + cw14_0 * wvr[i + 14];
                            float conv1 = l1 + hh1 + cw14_1 * wvr[i + 14];
                            float p0 = xv[i].x + hx2.x + conv0;
                            float p1 = xv[i].y + hx2.y + conv1;
                            float s = fmaxf(p0, 0.0f) * aw0 + fmaxf(p1, 0.0f) * aw1;
                            s = warp_sum(s);
                            if (lane == 0) sm.p2.part[tw][tl0 + i] = s;
                        }
                    }
                    {   // odd i
                        u64 Po[11];
                        #pragma unroll
                        for (int m = 0; m < 11; m++)
                            Po[m] = pack2(wvr[2 * m + 1], wvr[2 * m + 2]);
                        #pragma unroll
                        for (int i = 1; i < 10; i += 2) {
                            int j = (i - 1) >> 1;
                            u64 a0 = pack2(cb0, 0.0f), a1 = pack2(cb1, 0.0f);
                            #pragma unroll
                            for (int m = 0; m < 7; m++) {
                                fma2(a0, cwp0[m], Po[j + m]);
                                fma2(a1, cwp1[m], Po[j + m]);
                            }
                            float l0, hh0, l1, hh1;
                            unpack2(a0, l0, hh0); unpack2(a1, l1, hh1);
                            float conv0 = l0 + hh0 + cw14_0 * wvr[i + 14];
                            float conv1 = l1 + hh1 + cw14_1 * wvr[i + 14];
                            float p0 = xv[i].x + hx2.x + conv0;
                            float p1 = xv[i].y + hx2.y + conv1;
                            float s = fmaxf(p0, 0.0f) * aw0 + fmaxf(p1, 0.0f) * aw1;
                            s = warp_sum(s);
                            if (lane == 0) sm.p2.part[tw][tl0 + i] = s;
                        }
                    }
                }
            } else {
                #pragma unroll 1
                for (int tc = 0; tc < 5; tc++) {
                    int tl0 = tbase + tc * 10;
                    float2 xv[10];
                    #pragma unroll
                    for (int i = 0; i < 10; i++)
                        xv[i] = xb2[(size_t)(T0 + tl0 + i) * (Hd / 2)];
                    #pragma unroll
                    for (int i = 0; i < 10; i++) {
                        float p0 = xv[i].x + hx2.x;
                        float p1 = xv[i].y + hx2.y;
                        float s = fmaxf(p0, 0.0f) * aw0 + fmaxf(p1, 0.0f) * aw1;
                        s = warp_sum(s);
                        if (lane == 0) sm.p2.part[tw][tl0 + i] = s;
                    }
                }
            }
            __syncthreads();
            if (tid < 100) {
                float s = 0.0f;
                #pragma unroll
                for (int c2 = 0; c2 < 8; c2++) s += sm.p2.part[c2][tid];
                g_scores[b * Tenc + T0 + tid] = s + attn_b[0];
            }
        }
        GRID_BARRIER();

        // ===== phase 3: softmax + PARTIAL context. block = (b, t-tile 100) ===
        {
            int b = bid >> 2;
            int tile = bid & 3;
            int T0 = tile * 100;

            float sv = (tid < Tenc) ? __ldcg(&g_scores[b * Tenc + tid]) : -1e30f;
            float m = warp_max(sv);
            if (lane == 0) sm.p3.red[w] = m;
            __syncthreads();
            float bm = -1e30f;
            #pragma unroll
            for (int j = 0; j < 16; j++) bm = fmaxf(bm, sm.p3.red[j]);

            float e = (tid < Tenc) ? __expf(sv - bm) : 0.0f;
            if (tid < Tenc) sm.p3.a[tid] = e;
            float sum = warp_sum(e);
            __syncthreads();
            if (lane == 0) sm.p3.red[w] = sum;
            __syncthreads();
            float tot = 0.0f;
            #pragma unroll
            for (int j = 0; j < 16; j++) tot += sm.p3.red[j];
            float inv = 1.0f / tot;

            const float* xb = x + (size_t)b * Tenc * Hd + (size_t)T0 * Hd + tid;
            float acc[5];
            #pragma unroll
            for (int j = 0; j < 5; j++) acc[j] = 0.0f;
            #pragma unroll 1
            for (int c = 0; c < 10; c++) {
                int i0 = c * 10;
                float xr[10];
                #pragma unroll
                for (int i = 0; i < 10; i++)
                    xr[i] = xb[(size_t)(i0 + i) * Hd];
                #pragma unroll
                for (int i = 0; i < 10; i++)
                    acc[i % 5] = fmaf(sm.p3.a[T0 + i0 + i], xr[i], acc[i % 5]);
            }
            float r = (acc[0] + acc[1]) + (acc[2] + acc[3]) + acc[4];
            g_ctxp[tile][b * Hd + tid] = r * inv;

            if (tid < 100)
                aligns[(size_t)b * Lsteps * Tenc + (size_t)t * Tenc + T0 + tid] =
                    sm.p3.a[T0 + tid] * inv;
        }
        GRID_BARRIER();
    }

    // ===== final fc for step 99 (hx in buffer 0) ============================
    {
        const int bt = bid & 3, vt = bid >> 2;
        const int b0 = bt << 3;
        const int v = (vt << 4) + w;

        for (int idx = tid; idx < 8 * Hd; idx += 512) {
            int bb = idx >> 9, i = idx & 511;
            int b = b0 + bb;
            float sxv = __ldcg(&g_ctxp[0][b * Hd + i]) +
                        __ldcg(&g_ctxp[1][b * Hd + i]) +
                        __ldcg(&g_ctxp[2][b * Hd + i]) +
                        __ldcg(&g_ctxp[3][b * Hd + i]);
            sm.pf.in[bb][i] = __ldcg(&g_hx[0][b * Hd + i]) + sxv;
        }
        __syncthreads();

        if (v < Vout) {
            const float* fw = fc_w + (size_t)v * Hd;
            float fac[8];
            #pragma unroll
            for (int bb = 0; bb < 8; bb++) fac[bb] = 0.0f;
            for (int i = lane; i < Hd; i += 32) {
                float wv = fw[i];
                #pragma unroll
                for (int bb = 0; bb < 8; bb++)
                    fac[bb] = fmaf(wv, sm.pf.in[bb][i], fac[bb]);
            }
            #pragma unroll
            for (int bb = 0; bb < 8; bb++) fac[bb] = warp_sum(fac[bb]);
            if (lane < 8) {
                int b = b0 + lane;
                out[(size_t)b * Lsteps * Vout + (size_t)(Lsteps - 1) * Vout + v] =
                    fac[lane] + fc_b[v];
            }
        }
    }
    #undef GRID_BARRIER
}

// ---------------- launch ------------------------------------------------------
extern "C" void kernel_launch(void* const* d_in, const int* in_sizes, int n_in,
                              void* d_out, int out_size)
{
    const float* x      = (const float*)d_in[0];
    const int*   y      = (const int*)  d_in[1];
    const float* emb    = (const float*)d_in[2];
    const float* W_ih   = (const float*)d_in[3];
    const float* W_hh   = (const float*)d_in[4];
    const float* b_ih   = (const float*)d_in[5];
    const float* b_hh   = (const float*)d_in[6];
    const float* conv_w = (const float*)d_in[7];
    const float* conv_b = (const float*)d_in[8];
    const float* attn_w = (const float*)d_in[9];
    const float* attn_b = (const float*)d_in[10];
    const float* fc_w   = (const float*)d_in[11];
    const float* fc_b   = (const float*)d_in[12];

    float* out    = (float*)d_out;
    float* aligns = out + (size_t)Bsz * Lsteps * Vout;

    bar_init<<<1, 1>>>();
    seq2seq_persist<<<NBLK, 512>>>(x, y, emb, W_ih, W_hh, b_ih, b_hh,
                                   conv_w, conv_b, attn_w, attn_b,
                                   fc_w, fc_b, out, aligns);
}

// round 12
// speedup vs baseline: 1.2710x; 1.0125x over previous
#include <cuda_runtime.h>

#define Bsz 32
#define Tenc 400
#define Hd 512
#define Lsteps 100
#define Vout 511
#define KS 15
#define NBLK 128

// ---------------- persistent state ------------------------------------------
__device__ float g_hx[2][Bsz * Hd];
__device__ float g_ctxp[4][Bsz * Hd];     // per-tile UNNORMALIZED partial ctx
__device__ float2 g_norm[4][Bsz][Lsteps]; // per-(tile,b,t): (m_loc, s_loc)
__device__ unsigned g_bar;                // zeroed by bar_init each launch

__device__ __forceinline__ float warp_sum(float v) {
    #pragma unroll
    for (int o = 16; o; o >>= 1) v += __shfl_xor_sync(0xffffffffu, v, o);
    return v;
}
__device__ __forceinline__ float warp_max(float v) {
    #pragma unroll
    for (int o = 16; o; o >>= 1) v = fmaxf(v, __shfl_xor_sync(0xffffffffu, v, o));
    return v;
}

// ---- f32x2 packed math ------------------------------------------------------
typedef unsigned long long u64;
__device__ __forceinline__ u64 pack2(float lo, float hi) {
    u64 r;
    asm("mov.b64 %0, {%1, %2};" : "=l"(r) : "f"(lo), "f"(hi));
    return r;
}
__device__ __forceinline__ void unpack2(u64 v, float& lo, float& hi) {
    asm("mov.b64 {%0, %1}, %2;" : "=f"(lo), "=f"(hi) : "l"(v));
}
__device__ __forceinline__ void fma2(u64& d, u64 a, u64 b) {
    asm("fma.rn.f32x2 %0, %1, %2, %0;" : "+l"(d) : "l"(a), "l"(b));
}

// exact flash renorm factors for (b, tstep): f[k] = exp(m_k - M) / S
__device__ __forceinline__ void norm_factors(int b, int tstep, float f[4]) {
    float2 n0 = __ldcg(&g_norm[0][b][tstep]);
    float2 n1 = __ldcg(&g_norm[1][b][tstep]);
    float2 n2 = __ldcg(&g_norm[2][b][tstep]);
    float2 n3 = __ldcg(&g_norm[3][b][tstep]);
    float M = fmaxf(fmaxf(n0.x, n1.x), fmaxf(n2.x, n3.x));
    float e0 = __expf(n0.x - M), e1 = __expf(n1.x - M);
    float e2 = __expf(n2.x - M), e3 = __expf(n3.x - M);
    float S = n0.y * e0 + n1.y * e1 + n2.y * e2 + n3.y * e3;
    float inv = 1.0f / S;
    f[0] = e0 * inv; f[1] = e1 * inv; f[2] = e2 * inv; f[3] = e3 * inv;
}

__global__ void bar_init() { g_bar = 0u; }

struct __align__(16) SmemT {
    union {
        struct { float2 ix[4][Hd]; float2 hx[4][Hd]; float2 fin[4][Hd];
                 float fnorm[8][4]; } p1;                       // 48KB + 128B
        struct { float in[8][Hd]; } pf;                          // 16KB
        struct { float win[128]; float part[8][100]; float a[128];
                 float red[16]; } p23;
        struct { float fac[128]; } fix;
    };
};

__global__ void __launch_bounds__(512, 1) seq2seq_persist(
    const float* __restrict__ x, const int* __restrict__ y,
    const float* __restrict__ emb,
    const float* __restrict__ W_ih, const float* __restrict__ W_hh,
    const float* __restrict__ b_ih, const float* __restrict__ b_hh,
    const float* __restrict__ conv_w, const float* __restrict__ conv_b,
    const float* __restrict__ attn_w, const float* __restrict__ attn_b,
    const float* __restrict__ fc_w, const float* __restrict__ fc_b,
    float* __restrict__ out, float* __restrict__ aligns)
{
    extern __shared__ __align__(16) char smraw[];
    SmemT& sm = *reinterpret_cast<SmemT*>(smraw);
    const int bid = blockIdx.x;
    const int tid = threadIdx.x;
    const int w = tid >> 5, lane = tid & 31;

    unsigned barn = 0;

    #define GRID_BARRIER() do {                                              \
        barn++;                                                              \
        __syncthreads();                                                     \
        if (tid == 0) {                                                      \
            __threadfence();                                                 \
            atomicAdd(&g_bar, 1u);                                           \
            unsigned target = barn * NBLK;                                   \
            while ((int)(*((volatile unsigned*)&g_bar) - target) < 0)        \
                __nanosleep(32);                                             \
        }                                                                    \
        __syncthreads();                                                     \
    } while (0)

    for (int t = 0; t < Lsteps; t++) {
        const int rd = t & 1, wr = rd ^ 1;

        // ===== phase 1: GRU + fc(t-1). block = (ht 16h, bt 8b); warp=(1h,8b)
        {
            const int bt = bid & 3, ht = bid >> 2;
            const int b0 = bt << 3;
            const int h = (ht << 4) + w;     // GRU output row == fc row

            if (t > 0 && tid < 8) {
                float f[4];
                norm_factors(b0 + tid, t - 1, f);
                sm.p1.fnorm[tid][0] = f[0]; sm.p1.fnorm[tid][1] = f[1];
                sm.p1.fnorm[tid][2] = f[2]; sm.p1.fnorm[tid][3] = f[3];
            }
            __syncthreads();

            for (int idx = tid; idx < 8 * (Hd / 4); idx += 512) {
                int bb = idx >> 7, i4 = (idx & 127) << 2;
                int b = b0 + bb;
                int tok = y[b * 101 + t];
                float4 sx4 = make_float4(0.f, 0.f, 0.f, 0.f);
                float4 hx4 = make_float4(0.f, 0.f, 0.f, 0.f);
                if (t > 0) {
                    float fn0 = sm.p1.fnorm[bb][0], fn1 = sm.p1.fnorm[bb][1];
                    float fn2 = sm.p1.fnorm[bb][2], fn3 = sm.p1.fnorm[bb][3];
                    float4 c0 = __ldcg((const float4*)&g_ctxp[0][b * Hd] + (i4 >> 2));
                    float4 c1 = __ldcg((const float4*)&g_ctxp[1][b * Hd] + (i4 >> 2));
                    float4 c2 = __ldcg((const float4*)&g_ctxp[2][b * Hd] + (i4 >> 2));
                    float4 c3 = __ldcg((const float4*)&g_ctxp[3][b * Hd] + (i4 >> 2));
                    sx4.x = c0.x * fn0 + c1.x * fn1 + c2.x * fn2 + c3.x * fn3;
                    sx4.y = c0.y * fn0 + c1.y * fn1 + c2.y * fn2 + c3.y * fn3;
                    sx4.z = c0.z * fn0 + c1.z * fn1 + c2.z * fn2 + c3.z * fn3;
                    sx4.w = c0.w * fn0 + c1.w * fn1 + c2.w * fn2 + c3.w * fn3;
                    hx4 = __ldcg((const float4*)&g_hx[rd][b * Hd] + (i4 >> 2));
                }
                float4 e = ((const float4*)emb)[(size_t)tok * (Hd / 4) + (i4 >> 2)];
                int p = bb >> 1, off = bb & 1;
                float* dix = (float*)&sm.p1.ix[p][i4] + off;
                float* dhx = (float*)&sm.p1.hx[p][i4] + off;
                float* dfn = (float*)&sm.p1.fin[p][i4] + off;
                dix[0] = e.x + sx4.x; dix[2] = e.y + sx4.y;
                dix[4] = e.z + sx4.z; dix[6] = e.w + sx4.w;
                dhx[0] = hx4.x; dhx[2] = hx4.y; dhx[4] = hx4.z; dhx[6] = hx4.w;
                dfn[0] = hx4.x + sx4.x; dfn[2] = hx4.y + sx4.y;
                dfn[4] = hx4.z + sx4.z; dfn[6] = hx4.w + sx4.w;
            }
            __syncthreads();

            const float* wi0 = W_ih + (size_t)h * Hd;
            const float* wi1 = W_ih + (size_t)(Hd + h) * Hd;
            const float* wi2 = W_ih + (size_t)(2 * Hd + h) * Hd;
            const float* wh0 = W_hh + (size_t)h * Hd;
            const float* wh1 = W_hh + (size_t)(Hd + h) * Hd;
            const float* wh2 = W_hh + (size_t)(2 * Hd + h) * Hd;
            const float* fw  = fc_w + (size_t)(h < Vout ? h : 0) * Hd;

            u64 acc2[6][4], fac2[4];
            #pragma unroll
            for (int g = 0; g < 6; g++)
                #pragma unroll
                for (int j = 0; j < 4; j++) acc2[g][j] = pack2(0.f, 0.f);
            #pragma unroll
            for (int j = 0; j < 4; j++) fac2[j] = pack2(0.f, 0.f);

            const u64* six = (const u64*)sm.p1.ix;
            const u64* shx = (const u64*)sm.p1.hx;
            const u64* sfn = (const u64*)sm.p1.fin;

            for (int i = lane; i < Hd; i += 32) {
                u64 W0 = pack2(wi0[i], wi0[i]);
                u64 W1 = pack2(wi1[i], wi1[i]);
                u64 W2 = pack2(wi2[i], wi2[i]);
                u64 W3 = pack2(wh0[i], wh0[i]);
                u64 W4 = pack2(wh1[i], wh1[i]);
                u64 W5 = pack2(wh2[i], wh2[i]);
                u64 W6 = pack2(fw[i],  fw[i]);
                #pragma unroll
                for (int j = 0; j < 4; j++) {
                    u64 xi = six[j * Hd + i];
                    u64 xh = shx[j * Hd + i];
                    u64 xf = sfn[j * Hd + i];
                    fma2(acc2[0][j], W0, xi);
                    fma2(acc2[1][j], W1, xi);
                    fma2(acc2[2][j], W2, xi);
                    fma2(acc2[3][j], W3, xh);
                    fma2(acc2[4][j], W4, xh);
                    fma2(acc2[5][j], W5, xh);
                    fma2(fac2[j],    W6, xf);
                }
            }

            float accs[6][8], facs[8];
            #pragma unroll
            for (int g = 0; g < 6; g++)
                #pragma unroll
                for (int j = 0; j < 4; j++)
                    unpack2(acc2[g][j], accs[g][2 * j], accs[g][2 * j + 1]);
            #pragma unroll
            for (int j = 0; j < 4; j++)
                unpack2(fac2[j], facs[2 * j], facs[2 * j + 1]);

            #pragma unroll
            for (int g = 0; g < 6; g++)
                #pragma unroll
                for (int bb = 0; bb < 8; bb++) accs[g][bb] = warp_sum(accs[g][bb]);
            #pragma unroll
            for (int bb = 0; bb < 8; bb++) facs[bb] = warp_sum(facs[bb]);

            if (lane < 8) {
                int bb = lane, b = b0 + bb;
                float gr = accs[0][bb] + b_ih[h] + accs[3][bb] + b_hh[h];
                float gz = accs[1][bb] + b_ih[Hd + h] + accs[4][bb] + b_hh[Hd + h];
                float r = 1.0f / (1.0f + expf(-gr));
                float z = 1.0f / (1.0f + expf(-gz));
                float n = tanhf(accs[2][bb] + b_ih[2 * Hd + h] +
                                r * (accs[5][bb] + b_hh[2 * Hd + h]));
                float2 hv = sm.p1.hx[bb >> 1][h];
                float hp = (bb & 1) ? hv.y : hv.x;
                g_hx[wr][b * Hd + h] = (1.0f - z) * n + z * hp;
                if (t > 0 && h < Vout)
                    out[(size_t)b * Lsteps * Vout + (size_t)(t - 1) * Vout + h] =
                        facs[bb] + fc_b[h];
            }
        }
        GRID_BARRIER();

        // ===== phase 2+3 (flash): scores -> local softmax -> partial ctx ====
        {
            int b = bid >> 2;
            int tile = bid & 3;
            int T0 = tile * 100;
            int tw = w & 7, thalf = w >> 3;
            int h0 = tw * 64 + lane * 2;

            if (tid < 114) {
                int j = T0 - 7 + tid;
                float vv = 0.0f;
                if (t > 0 && j >= 0 && j < Tenc) {
                    float f[4];
                    norm_factors(b, t - 1, f);
                    int k = j / 100;
                    vv = __ldcg(&aligns[(size_t)b * Lsteps * Tenc +
                                        (size_t)(t - 1) * Tenc + j]) * f[k];
                }
                sm.p23.win[tid] = vv;
            }

            u64 cwp0[7], cwp1[7];
            float cw14_0, cw14_1;
            {
                const float* c0p = conv_w + h0 * KS;
                const float* c1p = conv_w + (h0 + 1) * KS;
                #pragma unroll
                for (int m = 0; m < 7; m++) {
                    cwp0[m] = pack2(c0p[2 * m], c0p[2 * m + 1]);
                    cwp1[m] = pack2(c1p[2 * m], c1p[2 * m + 1]);
                }
                cw14_0 = c0p[14]; cw14_1 = c1p[14];
            }
            float cb0 = conv_b[h0],  cb1 = conv_b[h0 + 1];
            float aw0 = attn_w[h0],  aw1 = attn_w[h0 + 1];
            float2 hx2 = __ldcg((const float2*)&g_hx[wr][b * Hd + h0]);
            __syncthreads();

            const float2* xb2 = (const float2*)(x + (size_t)b * Tenc * Hd) + (h0 >> 1);
            const int tbase = thalf * 50;

            if (t > 0) {
                #pragma unroll 1
                for (int tc = 0; tc < 5; tc++) {
                    int tl0 = tbase + tc * 10;
                    float2 xv[10];
                    #pragma unroll
                    for (int i = 0; i < 10; i++)
                        xv[i] = xb2[(size_t)(T0 + tl0 + i) * (Hd / 2)];
                    float wvr[24];
                    #pragma unroll
                    for (int j = 0; j < 24; j++) wvr[j] = sm.p23.win[tl0 + j];

                    {   // even i
                        u64 Pe[11];
                        #pragma unroll
                        for (int m = 0; m < 11; m++)
                            Pe[m] = pack2(wvr[2 * m], wvr[2 * m + 1]);
                        #pragma unroll
                        for (int i = 0; i < 10; i += 2) {
                            int j = i >> 1;
                            u64 a0 = pack2(cb0, 0.0f), a1 = pack2(cb1, 0.0f);
                            #pragma unroll
                            for (int m = 0; m < 7; m++) {
                                fma2(a0, cwp0[m], Pe[j + m]);
                                fma2(a1, cwp1[m], Pe[j + m]);
                            }
                            float l0, hh0, l1, hh1;
                            unpack2(a0, l0, hh0); unpack2(a1, l1, hh1);
                            float conv0 = l0 + hh0 + cw14_0 * wvr[i + 14];
                            float conv1 = l1 + hh1 + cw14_1 * wvr[i + 14];
                            float p0 = xv[i].x + hx2.x + conv0;
                            float p1 = xv[i].y + hx2.y + conv1;
                            float s = fmaxf(p0, 0.0f) * aw0 + fmaxf(p1, 0.0f) * aw1;
                            s = warp_sum(s);
                            if (lane == 0) sm.p23.part[tw][tl0 + i] = s;
                        }
                    }
                    {   // odd i
                        u64 Po[11];
                        #pragma unroll
                        for (int m = 0; m < 11; m++)
                            Po[m] = pack2(wvr[2 * m + 1], wvr[2 * m + 2]);
                        #pragma unroll
                        for (int i = 1; i < 10; i += 2) {
                            int j = (i - 1) >> 1;
                            u64 a0 = pack2(cb0, 0.0f), a1 = pack2(cb1, 0.0f);
                            #pragma unroll
                            for (int m = 0; m < 7; m++) {
                                fma2(a0, cwp0[m], Po[j + m]);
                                fma2(a1, cwp1[m], Po[j + m]);
                            }
                            float l0, hh0, l1, hh1;
                            unpack2(a0, l0, hh0); unpack2(a1, l1, hh1);
                            float conv0 = l0 + hh0 + cw14_0 * wvr[i + 14];
                            float conv1 = l1 + hh1 + cw14_1 * wvr[i + 14];
                            float p0 = xv[i].x + hx2.x + conv0;
                            float p1 = xv[i].y + hx2.y + conv1;
                            float s = fmaxf(p0, 0.0f) * aw0 + fmaxf(p1, 0.0f) * aw1;
                            s = warp_sum(s);
                            if (lane == 0) sm.p23.part[tw][tl0 + i] = s;
                        }
                    }
                }
            } else {
                #pragma unroll 1
                for (int tc = 0; tc < 5; tc++) {
                    int tl0 = tbase + tc * 10;
                    float2 xv[10];
                    #pragma unroll
                    for (int i = 0; i < 10; i++)
                        xv[i] = xb2[(size_t)(T0 + tl0 + i) * (Hd / 2)];
                    #pragma unroll
                    for (int i = 0; i < 10; i++) {
                        float p0 = xv[i].x + hx2.x;
                        float p1 = xv[i].y + hx2.y;
                        float s = fmaxf(p0, 0.0f) * aw0 + fmaxf(p1, 0.0f) * aw1;
                        s = warp_sum(s);
                        if (lane == 0) sm.p23.part[tw][tl0 + i] = s;
                    }
                }
            }
            __syncthreads();

            // scores -> sm.a (padded to 128)
            if (tid < 128) {
                float sc = -1e30f;
                if (tid < 100) {
                    float s = 0.0f;
                    #pragma unroll
                    for (int c2 = 0; c2 < 8; c2++) s += sm.p23.part[c2][tid];
                    sc = s + attn_b[0];
                }
                sm.p23.a[tid] = sc;
            }
            __syncthreads();

            // local softmax over this tile's 100 scores
            float m_loc, s_loc;
            if (tid < 128) {
                float v = sm.p23.a[tid];
                float mm = warp_max(v);
                if (lane == 0) sm.p23.red[w] = mm;
            }
            __syncthreads();
            m_loc = fmaxf(fmaxf(sm.p23.red[0], sm.p23.red[1]),
                          fmaxf(sm.p23.red[2], sm.p23.red[3]));
            if (tid < 128) {
                float e = (tid < 100) ? __expf(sm.p23.a[tid] - m_loc) : 0.0f;
                sm.p23.a[tid] = e;
                float ss = warp_sum(e);
                if (lane == 0) sm.p23.red[8 + w] = ss;
            }
            __syncthreads();
            s_loc = (sm.p23.red[8] + sm.p23.red[9]) +
                    (sm.p23.red[10] + sm.p23.red[11]);

            if (tid == 0) g_norm[tile][b][t] = make_float2(m_loc, s_loc);
            if (tid < 100)
                aligns[(size_t)b * Lsteps * Tenc + (size_t)t * Tenc + T0 + tid] =
                    sm.p23.a[tid];   // UNNORMALIZED e; fixed in epilogue

            // partial (unnormalized) context for this tile
            {
                const float* xb = x + (size_t)b * Tenc * Hd + (size_t)T0 * Hd + tid;
                float acc[5];
                #pragma unroll
                for (int j = 0; j < 5; j++) acc[j] = 0.0f;
                #pragma unroll 1
                for (int c = 0; c < 10; c++) {
                    int i0 = c * 10;
                    float xr[10];
                    #pragma unroll
                    for (int i = 0; i < 10; i++)
                        xr[i] = xb[(size_t)(i0 + i) * Hd];
                    #pragma unroll
                    for (int i = 0; i < 10; i++)
                        acc[i % 5] = fmaf(sm.p23.a[i0 + i], xr[i], acc[i % 5]);
                }
                float r = (acc[0] + acc[1]) + (acc[2] + acc[3]) + acc[4];
                g_ctxp[tile][b * Hd + tid] = r;
            }
        }
        GRID_BARRIER();
    }

    // ===== epilogue A: normalize aligns in place. block = (b, tile) =========
    {
        int b = bid >> 2;
        int tile = bid & 3;
        int T0 = tile * 100;
        if (tid < 100) {
            float f[4];
            norm_factors(b, tid, f);
            sm.fix.fac[tid] = f[tile];
        }
        __syncthreads();
        for (int idx = tid; idx < 100 * 100; idx += 512) {
            int tp = idx / 100, j = idx - tp * 100;
            size_t off = (size_t)b * Lsteps * Tenc + (size_t)tp * Tenc + T0 + j;
            aligns[off] *= sm.fix.fac[tp];
        }
    }
    __syncthreads();

    // ===== epilogue B: final fc for step 99 (hx in buffer 0) ================
    {
        const int bt = bid & 3, vt = bid >> 2;
        const int b0 = bt << 3;
        const int v = (vt << 4) + w;

        if (tid < 8) {
            float f[4];
            norm_factors(b0 + tid, Lsteps - 1, f);
            sm.p1.fnorm[tid][0] = f[0]; sm.p1.fnorm[tid][1] = f[1];
            sm.p1.fnorm[tid][2] = f[2]; sm.p1.fnorm[tid][3] = f[3];
        }
        __syncthreads();

        for (int idx = tid; idx < 8 * Hd; idx += 512) {
            int bb = idx >> 9, i = idx & 511;
            int b = b0 + bb;
            float fn0 = sm.p1.fnorm[bb][0], fn1 = sm.p1.fnorm[bb][1];
            float fn2 = sm.p1.fnorm[bb][2], fn3 = sm.p1.fnorm[bb][3];
            float sxv = __ldcg(&g_ctxp[0][b * Hd + i]) * fn0 +
                        __ldcg(&g_ctxp[1][b * Hd + i]) * fn1 +
                        __ldcg(&g_ctxp[2][b * Hd + i]) * fn2 +
                        __ldcg(&g_ctxp[3][b * Hd + i]) * fn3;
            sm.pf.in[bb][i] = __ldcg(&g_hx[0][b * Hd + i]) + sxv;
        }
        __syncthreads();

        if (v < Vout) {
            const float* fw = fc_w + (size_t)v * Hd;
            float fac[8];
            #pragma unroll
            for (int bb = 0; bb < 8; bb++) fac[bb] = 0.0f;
            for (int i = lane; i < Hd; i += 32) {
                float wv = fw[i];
                #pragma unroll
                for (int bb = 0; bb < 8; bb++)
                    fac[bb] = fmaf(wv, sm.pf.in[bb][i], fac[bb]);
            }
            #pragma unroll
            for (int bb = 0; bb < 8; bb++) fac[bb] = warp_sum(fac[bb]);
            if (lane < 8) {
                int b = b0 + lane;
                out[(size_t)b * Lsteps * Vout + (size_t)(Lsteps - 1) * Vout + v] =
                    fac[lane] + fc_b[v];
            }
        }
    }
    #undef GRID_BARRIER
}

// ---------------- launch ------------------------------------------------------
extern "C" void kernel_launch(void* const* d_in, const int* in_sizes, int n_in,
                              void* d_out, int out_size)
{
    const float* x      = (const float*)d_in[0];
    const int*   y      = (const int*)  d_in[1];
    const float* emb    = (const float*)d_in[2];
    const float* W_ih   = (const float*)d_in[3];
    const float* W_hh   = (const float*)d_in[4];
    const float* b_ih   = (const float*)d_in[5];
    const float* b_hh   = (const float*)d_in[6];
    const float* conv_w = (const float*)d_in[7];
    const float* conv_b = (const float*)d_in[8];
    const float* attn_w = (const float*)d_in[9];
    const float* attn_b = (const float*)d_in[10];
    const float* fc_w   = (const float*)d_in[11];
    const float* fc_b   = (const float*)d_in[12];

    float* out    = (float*)d_out;
    float* aligns = out + (size_t)Bsz * Lsteps * Vout;

    static const int smem_sz = (int)sizeof(SmemT);
    cudaFuncSetAttribute(seq2seq_persist,
                         cudaFuncAttributeMaxDynamicSharedMemorySize, smem_sz);

    bar_init<<<1, 1>>>();
    seq2seq_persist<<<NBLK, 512, smem_sz>>>(x, y, emb, W_ih, W_hh, b_ih, b_hh,
                                            conv_w, conv_b, attn_w, attn_b,
                                            fc_w, fc_b, out, aligns);
}

// round 13
// speedup vs baseline: 1.3316x; 1.0477x over previous
#include <cuda_runtime.h>

#define Bsz 32
#define Tenc 400
#define Hd 512
#define Lsteps 100
#define Vout 511
#define KS 15
#define NBLK 128
#define GBLK 32    // blocks per group; group g owns batch octet g

// ---------------- persistent state ------------------------------------------
__device__ float g_hx[2][Bsz * Hd];
__device__ float g_ctxp[4][Bsz * Hd];     // per-tile UNNORMALIZED partial ctx
__device__ float2 g_norm[4][Bsz][Lsteps]; // per-(tile,b,t): (m_loc, s_loc)
__device__ unsigned g_bars[4];            // per-group barrier counters

__device__ __forceinline__ float warp_sum(float v) {
    #pragma unroll
    for (int o = 16; o; o >>= 1) v += __shfl_xor_sync(0xffffffffu, v, o);
    return v;
}
__device__ __forceinline__ float warp_max(float v) {
    #pragma unroll
    for (int o = 16; o; o >>= 1) v = fmaxf(v, __shfl_xor_sync(0xffffffffu, v, o));
    return v;
}

// ---- f32x2 packed math ------------------------------------------------------
typedef unsigned long long u64;
__device__ __forceinline__ u64 pack2(float lo, float hi) {
    u64 r;
    asm("mov.b64 %0, {%1, %2};" : "=l"(r) : "f"(lo), "f"(hi));
    return r;
}
__device__ __forceinline__ void unpack2(u64 v, float& lo, float& hi) {
    asm("mov.b64 {%0, %1}, %2;" : "=f"(lo), "=f"(hi) : "l"(v));
}
__device__ __forceinline__ void fma2(u64& d, u64 a, u64 b) {
    asm("fma.rn.f32x2 %0, %1, %2, %0;" : "+l"(d) : "l"(a), "l"(b));
}
// packed butterfly reduction: returns elementwise lane-sum of the f32x2 pair
__device__ __forceinline__ u64 warp_sum2(u64 v) {
    #pragma unroll
    for (int o = 16; o; o >>= 1) {
        u64 s = __shfl_xor_sync(0xffffffffu, v, o);
        asm("add.rn.f32x2 %0, %0, %1;" : "+l"(v) : "l"(s));
    }
    return v;
}

// exact flash renorm factors for (b, tstep): f[k] = exp(m_k - M) / S
__device__ __forceinline__ void norm_factors(int b, int tstep, float f[4]) {
    float2 n0 = __ldcg(&g_norm[0][b][tstep]);
    float2 n1 = __ldcg(&g_norm[1][b][tstep]);
    float2 n2 = __ldcg(&g_norm[2][b][tstep]);
    float2 n3 = __ldcg(&g_norm[3][b][tstep]);
    float M = fmaxf(fmaxf(n0.x, n1.x), fmaxf(n2.x, n3.x));
    float e0 = __expf(n0.x - M), e1 = __expf(n1.x - M);
    float e2 = __expf(n2.x - M), e3 = __expf(n3.x - M);
    float S = n0.y * e0 + n1.y * e1 + n2.y * e2 + n3.y * e3;
    float inv = 1.0f / S;
    f[0] = e0 * inv; f[1] = e1 * inv; f[2] = e2 * inv; f[3] = e3 * inv;
}

__global__ void bar_init() {
    g_bars[0] = 0u; g_bars[1] = 0u; g_bars[2] = 0u; g_bars[3] = 0u;
}

struct __align__(16) SmemT {
    union {
        struct { float2 ix[4][Hd]; float2 hx[4][Hd]; float2 fin[4][Hd];
                 float fnorm[8][4]; } p1;                       // 48KB + 128B
        struct { float in[8][Hd]; } pf;                          // 16KB
        struct { float win[128]; float part[8][100]; float a[128];
                 float red[16]; } p23;
        struct { float fac[128]; } fix;
    };
};

__global__ void __launch_bounds__(512, 1) seq2seq_persist(
    const float* __restrict__ x, const int* __restrict__ y,
    const float* __restrict__ emb,
    const float* __restrict__ W_ih, const float* __restrict__ W_hh,
    const float* __restrict__ b_ih, const float* __restrict__ b_hh,
    const float* __restrict__ conv_w, const float* __restrict__ conv_b,
    const float* __restrict__ attn_w, const float* __restrict__ attn_b,
    const float* __restrict__ fc_w, const float* __restrict__ fc_b,
    float* __restrict__ out, float* __restrict__ aligns)
{
    extern __shared__ __align__(16) char smraw[];
    SmemT& sm = *reinterpret_cast<SmemT*>(smraw);
    const int bid  = blockIdx.x;
    const int grp  = bid >> 5;          // batch octet 0..3
    const int lblk = bid & 31;          // block within group
    const int b0   = grp << 3;
    const int tid  = threadIdx.x;
    const int w = tid >> 5, lane = tid & 31;

    unsigned barn = 0;

    #define GRID_BARRIER() do {                                              \
        barn++;                                                              \
        __syncthreads();                                                     \
        if (tid == 0) {                                                      \
            __threadfence();                                                 \
            atomicAdd(&g_bars[grp], 1u);                                     \
            unsigned target = barn * GBLK;                                   \
            while ((int)(*((volatile unsigned*)&g_bars[grp]) - target) < 0)  \
                __nanosleep(32);                                             \
        }                                                                    \
        __syncthreads();                                                     \
    } while (0)

    for (int t = 0; t < Lsteps; t++) {
        const int rd = t & 1, wr = rd ^ 1;

        // ===== phase 1: GRU + fc(t-1). block = (16 h-rows, 8 b); warp=(1h,8b)
        {
            const int h = (lblk << 4) + w;   // GRU output row == fc row

            if (t > 0 && tid < 8) {
                float f[4];
                norm_factors(b0 + tid, t - 1, f);
                sm.p1.fnorm[tid][0] = f[0]; sm.p1.fnorm[tid][1] = f[1];
                sm.p1.fnorm[tid][2] = f[2]; sm.p1.fnorm[tid][3] = f[3];
            }
            __syncthreads();

            for (int idx = tid; idx < 8 * (Hd / 4); idx += 512) {
                int bb = idx >> 7, i4 = (idx & 127) << 2;
                int b = b0 + bb;
                int tok = y[b * 101 + t];
                float4 sx4 = make_float4(0.f, 0.f, 0.f, 0.f);
                float4 hx4 = make_float4(0.f, 0.f, 0.f, 0.f);
                if (t > 0) {
                    float fn0 = sm.p1.fnorm[bb][0], fn1 = sm.p1.fnorm[bb][1];
                    float fn2 = sm.p1.fnorm[bb][2], fn3 = sm.p1.fnorm[bb][3];
                    float4 c0 = __ldcg((const float4*)&g_ctxp[0][b * Hd] + (i4 >> 2));
                    float4 c1 = __ldcg((const float4*)&g_ctxp[1][b * Hd] + (i4 >> 2));
                    float4 c2 = __ldcg((const float4*)&g_ctxp[2][b * Hd] + (i4 >> 2));
                    float4 c3 = __ldcg((const float4*)&g_ctxp[3][b * Hd] + (i4 >> 2));
                    sx4.x = c0.x * fn0 + c1.x * fn1 + c2.x * fn2 + c3.x * fn3;
                    sx4.y = c0.y * fn0 + c1.y * fn1 + c2.y * fn2 + c3.y * fn3;
                    sx4.z = c0.z * fn0 + c1.z * fn1 + c2.z * fn2 + c3.z * fn3;
                    sx4.w = c0.w * fn0 + c1.w * fn1 + c2.w * fn2 + c3.w * fn3;
                    hx4 = __ldcg((const float4*)&g_hx[rd][b * Hd] + (i4 >> 2));
                }
                float4 e = ((const float4*)emb)[(size_t)tok * (Hd / 4) + (i4 >> 2)];
                int p = bb >> 1, off = bb & 1;
                float* dix = (float*)&sm.p1.ix[p][i4] + off;
                float* dhx = (float*)&sm.p1.hx[p][i4] + off;
                float* dfn = (float*)&sm.p1.fin[p][i4] + off;
                dix[0] = e.x + sx4.x; dix[2] = e.y + sx4.y;
                dix[4] = e.z + sx4.z; dix[6] = e.w + sx4.w;
                dhx[0] = hx4.x; dhx[2] = hx4.y; dhx[4] = hx4.z; dhx[6] = hx4.w;
                dfn[0] = hx4.x + sx4.x; dfn[2] = hx4.y + sx4.y;
                dfn[4] = hx4.z + sx4.z; dfn[6] = hx4.w + sx4.w;
            }
            __syncthreads();

            const float* wi0 = W_ih + (size_t)h * Hd;
            const float* wi1 = W_ih + (size_t)(Hd + h) * Hd;
            const float* wi2 = W_ih + (size_t)(2 * Hd + h) * Hd;
            const float* wh0 = W_hh + (size_t)h * Hd;
            const float* wh1 = W_hh + (size_t)(Hd + h) * Hd;
            const float* wh2 = W_hh + (size_t)(2 * Hd + h) * Hd;
            const float* fw  = fc_w + (size_t)(h < Vout ? h : 0) * Hd;

            u64 acc2[6][4], fac2[4];
            #pragma unroll
            for (int g = 0; g < 6; g++)
                #pragma unroll
                for (int j = 0; j < 4; j++) acc2[g][j] = pack2(0.f, 0.f);
            #pragma unroll
            for (int j = 0; j < 4; j++) fac2[j] = pack2(0.f, 0.f);

            const u64* six = (const u64*)sm.p1.ix;
            const u64* shx = (const u64*)sm.p1.hx;
            const u64* sfn = (const u64*)sm.p1.fin;

            for (int i = lane; i < Hd; i += 32) {
                u64 W0 = pack2(wi0[i], wi0[i]);
                u64 W1 = pack2(wi1[i], wi1[i]);
                u64 W2 = pack2(wi2[i], wi2[i]);
                u64 W3 = pack2(wh0[i], wh0[i]);
                u64 W4 = pack2(wh1[i], wh1[i]);
                u64 W5 = pack2(wh2[i], wh2[i]);
                u64 W6 = pack2(fw[i],  fw[i]);
                #pragma unroll
                for (int j = 0; j < 4; j++) {
                    u64 xi = six[j * Hd + i];
                    u64 xh = shx[j * Hd + i];
                    u64 xf = sfn[j * Hd + i];
                    fma2(acc2[0][j], W0, xi);
                    fma2(acc2[1][j], W1, xi);
                    fma2(acc2[2][j], W2, xi);
                    fma2(acc2[3][j], W3, xh);
                    fma2(acc2[4][j], W4, xh);
                    fma2(acc2[5][j], W5, xh);
                    fma2(fac2[j],    W6, xf);
                }
            }

            // packed butterfly reductions (28 u64 instead of 56 scalars)
            #pragma unroll
            for (int g = 0; g < 6; g++)
                #pragma unroll
                for (int j = 0; j < 4; j++) acc2[g][j] = warp_sum2(acc2[g][j]);
            #pragma unroll
            for (int j = 0; j < 4; j++) fac2[j] = warp_sum2(fac2[j]);

            float accs[6][8], facs[8];
            #pragma unroll
            for (int g = 0; g < 6; g++)
                #pragma unroll
                for (int j = 0; j < 4; j++)
                    unpack2(acc2[g][j], accs[g][2 * j], accs[g][2 * j + 1]);
            #pragma unroll
            for (int j = 0; j < 4; j++)
                unpack2(fac2[j], facs[2 * j], facs[2 * j + 1]);

            if (lane < 8) {
                int bb = lane, b = b0 + bb;
                float gr = accs[0][bb] + b_ih[h] + accs[3][bb] + b_hh[h];
                float gz = accs[1][bb] + b_ih[Hd + h] + accs[4][bb] + b_hh[Hd + h];
                float r = 1.0f / (1.0f + expf(-gr));
                float z = 1.0f / (1.0f + expf(-gz));
                float n = tanhf(accs[2][bb] + b_ih[2 * Hd + h] +
                                r * (accs[5][bb] + b_hh[2 * Hd + h]));
                float2 hv = sm.p1.hx[bb >> 1][h];
                float hp = (bb & 1) ? hv.y : hv.x;
                g_hx[wr][b * Hd + h] = (1.0f - z) * n + z * hp;
                if (t > 0 && h < Vout)
                    out[(size_t)b * Lsteps * Vout + (size_t)(t - 1) * Vout + h] =
                        facs[bb] + fc_b[h];
            }
        }
        GRID_BARRIER();

        // ===== phase 2+3 (flash): scores -> local softmax -> partial ctx ====
        {
            int b = b0 + (lblk >> 2);
            int tile = lblk & 3;
            int T0 = tile * 100;
            int tw = w & 7, thalf = w >> 3;
            int h0 = tw * 64 + lane * 2;

            if (tid < 114) {
                int j = T0 - 7 + tid;
                float vv = 0.0f;
                if (t > 0 && j >= 0 && j < Tenc) {
                    float f[4];
                    norm_factors(b, t - 1, f);
                    int k = j / 100;
                    vv = __ldcg(&aligns[(size_t)b * Lsteps * Tenc +
                                        (size_t)(t - 1) * Tenc + j]) * f[k];
                }
                sm.p23.win[tid] = vv;
            }

            u64 cwp0[7], cwp1[7];
            float cw14_0, cw14_1;
            {
                const float* c0p = conv_w + h0 * KS;
                const float* c1p = conv_w + (h0 + 1) * KS;
                #pragma unroll
                for (int m = 0; m < 7; m++) {
                    cwp0[m] = pack2(c0p[2 * m], c0p[2 * m + 1]);
                    cwp1[m] = pack2(c1p[2 * m], c1p[2 * m + 1]);
                }
                cw14_0 = c0p[14]; cw14_1 = c1p[14];
            }
            float cb0 = conv_b[h0],  cb1 = conv_b[h0 + 1];
            float aw0 = attn_w[h0],  aw1 = attn_w[h0 + 1];
            float2 hx2 = __ldcg((const float2*)&g_hx[wr][b * Hd + h0]);
            __syncthreads();

            const float2* xb2 = (const float2*)(x + (size_t)b * Tenc * Hd) + (h0 >> 1);
            const int tbase = thalf * 50;

            if (t > 0) {
                #pragma unroll 1
                for (int tc = 0; tc < 5; tc++) {
                    int tl0 = tbase + tc * 10;
                    float2 xv[10];
                    #pragma unroll
                    for (int i = 0; i < 10; i++)
                        xv[i] = xb2[(size_t)(T0 + tl0 + i) * (Hd / 2)];
                    float wvr[24];
                    #pragma unroll
                    for (int j = 0; j < 24; j++) wvr[j] = sm.p23.win[tl0 + j];

                    {   // even i
                        u64 Pe[11];
                        #pragma unroll
                        for (int m = 0; m < 11; m++)
                            Pe[m] = pack2(wvr[2 * m], wvr[2 * m + 1]);
                        #pragma unroll
                        for (int i = 0; i < 10; i += 2) {
                            int j = i >> 1;
                            u64 a0 = pack2(cb0, 0.0f), a1 = pack2(cb1, 0.0f);
                            #pragma unroll
                            for (int m = 0; m < 7; m++) {
                                fma2(a0, cwp0[m], Pe[j + m]);
                                fma2(a1, cwp1[m], Pe[j + m]);
                            }
                            float l0, hh0, l1, hh1;
                            unpack2(a0, l0, hh0); unpack2(a1, l1, hh1);
                            float conv0 = l0 + hh0 + cw14_0 * wvr[i + 14];
                            float conv1 = l1 + hh1 + cw14_1 * wvr[i + 14];
                            float p0 = xv[i].x + hx2.x + conv0;
                            float p1 = xv[i].y + hx2.y + conv1;
                            float s = fmaxf(p0, 0.0f) * aw0 + fmaxf(p1, 0.0f) * aw1;
                            s = warp_sum(s);
                            if (lane == 0) sm.p23.part[tw][tl0 + i] = s;
                        }
                    }
                    {   // odd i
                        u64 Po[11];
                        #pragma unroll
                        for (int m = 0; m < 11; m++)
                            Po[m] = pack2(wvr[2 * m + 1], wvr[2 * m + 2]);
                        #pragma unroll
                        for (int i = 1; i < 10; i += 2) {
                            int j = (i - 1) >> 1;
                            u64 a0 = pack2(cb0, 0.0f), a1 = pack2(cb1, 0.0f);
                            #pragma unroll
                            for (int m = 0; m < 7; m++) {
                                fma2(a0, cwp0[m], Po[j + m]);
                                fma2(a1, cwp1[m], Po[j + m]);
                            }
                            float l0, hh0, l1, hh1;
                            unpack2(a0, l0, hh0); unpack2(a1, l1, hh1);
                            float conv0 = l0 + hh0 + cw14_0 * wvr[i + 14];
                            float conv1 = l1 + hh1 + cw14_1 * wvr[i + 14];
                            float p0 = xv[i].x + hx2.x + conv0;
                            float p1 = xv[i].y + hx2.y + conv1;
                            float s = fmaxf(p0, 0.0f) * aw0 + fmaxf(p1, 0.0f) * aw1;
                            s = warp_sum(s);
                            if (lane == 0) sm.p23.part[tw][tl0 + i] = s;
                        }
                    }
                }
            } else {
                #pragma unroll 1
                for (int tc = 0; tc < 5; tc++) {
                    int tl0 = tbase + tc * 10;
                    float2 xv[10];
                    #pragma unroll
                    for (int i = 0; i < 10; i++)
                        xv[i] = xb2[(size_t)(T0 + tl0 + i) * (Hd / 2)];
                    #pragma unroll
                    for (int i = 0; i < 10; i++) {
                        float p0 = xv[i].x + hx2.x;
                        float p1 = xv[i].y + hx2.y;
                        float s = fmaxf(p0, 0.0f) * aw0 + fmaxf(p1, 0.0f) * aw1;
                        s = warp_sum(s);
                        if (lane == 0) sm.p23.part[tw][tl0 + i] = s;
                    }
                }
            }
            __syncthreads();

            // scores -> sm.a (padded to 128)
            if (tid < 128) {
                float sc = -1e30f;
                if (tid < 100) {
                    float s = 0.0f;
                    #pragma unroll
                    for (int c2 = 0; c2 < 8; c2++) s += sm.p23.part[c2][tid];
                    sc = s + attn_b[0];
                }
                sm.p23.a[tid] = sc;
            }
            __syncthreads();

            // local softmax over this tile's 100 scores
            float m_loc, s_loc;
            if (tid < 128) {
                float v = sm.p23.a[tid];
                float mm = warp_max(v);
                if (lane == 0) sm.p23.red[w] = mm;
            }
            __syncthreads();
            m_loc = fmaxf(fmaxf(sm.p23.red[0], sm.p23.red[1]),
                          fmaxf(sm.p23.red[2], sm.p23.red[3]));
            if (tid < 128) {
                float e = (tid < 100) ? __expf(sm.p23.a[tid] - m_loc) : 0.0f;
                sm.p23.a[tid] = e;
                float ss = warp_sum(e);
                if (lane == 0) sm.p23.red[8 + w] = ss;
            }
            __syncthreads();
            s_loc = (sm.p23.red[8] + sm.p23.red[9]) +
                    (sm.p23.red[10] + sm.p23.red[11]);

            if (tid == 0) g_norm[tile][b][t] = make_float2(m_loc, s_loc);
            if (tid < 100)
                aligns[(size_t)b * Lsteps * Tenc + (size_t)t * Tenc + T0 + tid] =
                    sm.p23.a[tid];   // UNNORMALIZED e; fixed in epilogue

            // partial (unnormalized) context for this tile
            {
                const float* xb = x + (size_t)b * Tenc * Hd + (size_t)T0 * Hd + tid;
                float acc[5];
                #pragma unroll
                for (int j = 0; j < 5; j++) acc[j] = 0.0f;
                #pragma unroll 1
                for (int c = 0; c < 10; c++) {
                    int i0 = c * 10;
                    float xr[10];
                    #pragma unroll
                    for (int i = 0; i < 10; i++)
                        xr[i] = xb[(size_t)(i0 + i) * Hd];
                    #pragma unroll
                    for (int i = 0; i < 10; i++)
                        acc[i % 5] = fmaf(sm.p23.a[i0 + i], xr[i], acc[i % 5]);
                }
                float r = (acc[0] + acc[1]) + (acc[2] + acc[3]) + acc[4];
                g_ctxp[tile][b * Hd + tid] = r;
            }
        }
        GRID_BARRIER();
    }

    // ===== epilogue A: normalize aligns in place. block = (b, tile) =========
    {
        int b = b0 + (lblk >> 2);
        int tile = lblk & 3;
        int T0 = tile * 100;
        if (tid < 100) {
            float f[4];
            norm_factors(b, tid, f);
            sm.fix.fac[tid] = f[tile];
        }
        __syncthreads();
        for (int idx = tid; idx < 100 * 100; idx += 512) {
            int tp = idx / 100, j = idx - tp * 100;
            size_t off = (size_t)b * Lsteps * Tenc + (size_t)tp * Tenc + T0 + j;
            aligns[off] *= sm.fix.fac[tp];
        }
    }
    __syncthreads();

    // ===== epilogue B: final fc for step 99 (hx in buffer 0) ================
    {
        const int v = (lblk << 4) + w;

        if (tid < 8) {
            float f[4];
            norm_factors(b0 + tid, Lsteps - 1, f);
            sm.p1.fnorm[tid][0] = f[0]; sm.p1.fnorm[tid][1] = f[1];
            sm.p1.fnorm[tid][2] = f[2]; sm.p1.fnorm[tid][3] = f[3];
        }
        __syncthreads();

        for (int idx = tid; idx < 8 * Hd; idx += 512) {
            int bb = idx >> 9, i = idx & 511;
            int b = b0 + bb;
            float fn0 = sm.p1.fnorm[bb][0], fn1 = sm.p1.fnorm[bb][1];
            float fn2 = sm.p1.fnorm[bb][2], fn3 = sm.p1.fnorm[bb][3];
            float sxv = __ldcg(&g_ctxp[0][b * Hd + i]) * fn0 +
                        __ldcg(&g_ctxp[1][b * Hd + i]) * fn1 +
                        __ldcg(&g_ctxp[2][b * Hd + i]) * fn2 +
                        __ldcg(&g_ctxp[3][b * Hd + i]) * fn3;
            sm.pf.in[bb][i] = __ldcg(&g_hx[0][b * Hd + i]) + sxv;
        }
        __syncthreads();

        if (v < Vout) {
            const float* fw = fc_w + (size_t)v * Hd;
            float fac[8];
            #pragma unroll
            for (int bb = 0; bb < 8; bb++) fac[bb] = 0.0f;
            for (int i = lane; i < Hd; i += 32) {
                float wv = fw[i];
                #pragma unroll
                for (int bb = 0; bb < 8; bb++)
                    fac[bb] = fmaf(wv, sm.pf.in[bb][i], fac[bb]);
            }
            #pragma unroll
            for (int bb = 0; bb < 8; bb++) fac[bb] = warp_sum(fac[bb]);
            if (lane < 8) {
                int b = b0 + lane;
                out[(size_t)b * Lsteps * Vout + (size_t)(Lsteps - 1) * Vout + v] =
                    fac[lane] + fc_b[v];
            }
        }
    }
    #undef GRID_BARRIER
}

// ---------------- launch ------------------------------------------------------
extern "C" void kernel_launch(void* const* d_in, const int* in_sizes, int n_in,
                              void* d_out, int out_size)
{
    const float* x      = (const float*)d_in[0];
    const int*   y      = (const int*)  d_in[1];
    const float* emb    = (const float*)d_in[2];
    const float* W_ih   = (const float*)d_in[3];
    const float* W_hh   = (const float*)d_in[4];
    const float* b_ih   = (const float*)d_in[5];
    const float* b_hh   = (const float*)d_in[6];
    const float* conv_w = (const float*)d_in[7];
    const float* conv_b = (const float*)d_in[8];
    const float* attn_w = (const float*)d_in[9];
    const float* attn_b = (const float*)d_in[10];
    const float* fc_w   = (const float*)d_in[11];
    const float* fc_b   = (const float*)d_in[12];

    float* out    = (float*)d_out;
    float* aligns = out + (size_t)Bsz * Lsteps * Vout;

    static const int smem_sz = (int)sizeof(SmemT);
    cudaFuncSetAttribute(seq2seq_persist,
                         cudaFuncAttributeMaxDynamicSharedMemorySize, smem_sz);

    bar_init<<<1, 1>>>();
    seq2seq_persist<<<NBLK, 512, smem_sz>>>(x, y, emb, W_ih, W_hh, b_ih, b_hh,
                                            conv_w, conv_b, attn_w, attn_b,
                                            fc_w, fc_b, out, aligns);
}

// round 14
// speedup vs baseline: 1.3835x; 1.0390x over previous
#include <cuda_runtime.h>

#define Bsz 32
#define Tenc 400
#define Hd 512
#define Lsteps 100
#define Vout 511
#define KS 15
#define NBLK 128
#define GBLK 32    // blocks per group; group g owns batch octet g

// ---------------- persistent state ------------------------------------------
__device__ float g_hx[2][Bsz * Hd];
__device__ float g_ctxp[4][Bsz * Hd];     // per-tile UNNORMALIZED partial ctx
__device__ float2 g_norm[4][Bsz][Lsteps]; // per-(tile,b,t): (m_loc, s_loc)
__device__ unsigned g_bars[4];            // per-group barrier counters

__device__ __forceinline__ float warp_sum(float v) {
    #pragma unroll
    for (int o = 16; o; o >>= 1) v += __shfl_xor_sync(0xffffffffu, v, o);
    return v;
}
__device__ __forceinline__ float warp_max(float v) {
    #pragma unroll
    for (int o = 16; o; o >>= 1) v = fmaxf(v, __shfl_xor_sync(0xffffffffu, v, o));
    return v;
}

// ---- f32x2 packed math ------------------------------------------------------
typedef unsigned long long u64;
__device__ __forceinline__ u64 pack2(float lo, float hi) {
    u64 r;
    asm("mov.b64 %0, {%1, %2};" : "=l"(r) : "f"(lo), "f"(hi));
    return r;
}
__device__ __forceinline__ void unpack2(u64 v, float& lo, float& hi) {
    asm("mov.b64 {%0, %1}, %2;" : "=f"(lo), "=f"(hi) : "l"(v));
}
__device__ __forceinline__ void fma2(u64& d, u64 a, u64 b) {
    asm("fma.rn.f32x2 %0, %1, %2, %0;" : "+l"(d) : "l"(a), "l"(b));
}
// packed butterfly reduction: elementwise lane-sum of the f32x2 pair
__device__ __forceinline__ u64 warp_sum2(u64 v) {
    #pragma unroll
    for (int o = 16; o; o >>= 1) {
        u64 s = __shfl_xor_sync(0xffffffffu, v, o);
        asm("add.rn.f32x2 %0, %0, %1;" : "+l"(v) : "l"(s));
    }
    return v;
}

// exact flash renorm factors for (b, tstep): f[k] = exp(m_k - M) / S
__device__ __forceinline__ void norm_factors(int b, int tstep, float f[4]) {
    float2 n0 = __ldcg(&g_norm[0][b][tstep]);
    float2 n1 = __ldcg(&g_norm[1][b][tstep]);
    float2 n2 = __ldcg(&g_norm[2][b][tstep]);
    float2 n3 = __ldcg(&g_norm[3][b][tstep]);
    float M = fmaxf(fmaxf(n0.x, n1.x), fmaxf(n2.x, n3.x));
    float e0 = __expf(n0.x - M), e1 = __expf(n1.x - M);
    float e2 = __expf(n2.x - M), e3 = __expf(n3.x - M);
    float S = n0.y * e0 + n1.y * e1 + n2.y * e2 + n3.y * e3;
    float inv = 1.0f / S;
    f[0] = e0 * inv; f[1] = e1 * inv; f[2] = e2 * inv; f[3] = e3 * inv;
}

__global__ void bar_init() {
    g_bars[0] = 0u; g_bars[1] = 0u; g_bars[2] = 0u; g_bars[3] = 0u;
}

struct __align__(16) SmemT {
    union {
        struct { float2 ix[4][Hd]; float2 hx[4][Hd]; float2 fin[4][Hd];
                 float fnorm[8][4]; } p1;                       // 48KB + 128B
        struct { float in[8][Hd]; } pf;                          // 16KB
        struct { float win[128]; float part[8][100]; float a[128];
                 float red[16]; } p23;
        struct { float fac[128]; } fix;
    };
};
// NOTE: p23.win (offset 0..512B) overlays p1.ix; win is written ONLY after
// BAR_ARRIVE's __syncthreads (all p1 smem reads complete), read after BAR_WAIT.

__global__ void __launch_bounds__(512, 1) seq2seq_persist(
    const float* __restrict__ x, const int* __restrict__ y,
    const float* __restrict__ emb,
    const float* __restrict__ W_ih, const float* __restrict__ W_hh,
    const float* __restrict__ b_ih, const float* __restrict__ b_hh,
    const float* __restrict__ conv_w, const float* __restrict__ conv_b,
    const float* __restrict__ attn_w, const float* __restrict__ attn_b,
    const float* __restrict__ fc_w, const float* __restrict__ fc_b,
    float* __restrict__ out, float* __restrict__ aligns)
{
    extern __shared__ __align__(16) char smraw[];
    SmemT& sm = *reinterpret_cast<SmemT*>(smraw);
    const int bid  = blockIdx.x;
    const int grp  = bid >> 5;          // batch octet 0..3
    const int lblk = bid & 31;          // block within group
    const int b0   = grp << 3;
    const int tid  = threadIdx.x;
    const int w = tid >> 5, lane = tid & 31;

    unsigned barn = 0;

    #define BAR_ARRIVE() do {                                                \
        barn++;                                                              \
        __syncthreads();                                                     \
        if (tid == 0) {                                                      \
            __threadfence();                                                 \
            atomicAdd(&g_bars[grp], 1u);                                     \
        }                                                                    \
    } while (0)
    #define BAR_WAIT() do {                                                  \
        if (tid == 0) {                                                      \
            unsigned target = barn * GBLK;                                   \
            while ((int)(*((volatile unsigned*)&g_bars[grp]) - target) < 0)  \
                __nanosleep(32);                                             \
        }                                                                    \
        __syncthreads();                                                     \
    } while (0)
    #define GRID_BARRIER() do { BAR_ARRIVE(); BAR_WAIT(); } while (0)

    for (int t = 0; t < Lsteps; t++) {
        const int rd = t & 1, wr = rd ^ 1;

        // ===== phase 1: GRU + fc(t-1). block = (16 h-rows, 8 b); warp=(1h,8b)
        {
            const int h = (lblk << 4) + w;   // GRU output row == fc row

            if (t > 0 && tid < 8) {
                float f[4];
                norm_factors(b0 + tid, t - 1, f);
                sm.p1.fnorm[tid][0] = f[0]; sm.p1.fnorm[tid][1] = f[1];
                sm.p1.fnorm[tid][2] = f[2]; sm.p1.fnorm[tid][3] = f[3];
            }
            __syncthreads();

            for (int idx = tid; idx < 8 * (Hd / 4); idx += 512) {
                int bb = idx >> 7, i4 = (idx & 127) << 2;
                int b = b0 + bb;
                int tok = y[b * 101 + t];
                float4 sx4 = make_float4(0.f, 0.f, 0.f, 0.f);
                float4 hx4 = make_float4(0.f, 0.f, 0.f, 0.f);
                if (t > 0) {
                    float fn0 = sm.p1.fnorm[bb][0], fn1 = sm.p1.fnorm[bb][1];
                    float fn2 = sm.p1.fnorm[bb][2], fn3 = sm.p1.fnorm[bb][3];
                    float4 c0 = __ldcg((const float4*)&g_ctxp[0][b * Hd] + (i4 >> 2));
                    float4 c1 = __ldcg((const float4*)&g_ctxp[1][b * Hd] + (i4 >> 2));
                    float4 c2 = __ldcg((const float4*)&g_ctxp[2][b * Hd] + (i4 >> 2));
                    float4 c3 = __ldcg((const float4*)&g_ctxp[3][b * Hd] + (i4 >> 2));
                    sx4.x = c0.x * fn0 + c1.x * fn1 + c2.x * fn2 + c3.x * fn3;
                    sx4.y = c0.y * fn0 + c1.y * fn1 + c2.y * fn2 + c3.y * fn3;
                    sx4.z = c0.z * fn0 + c1.z * fn1 + c2.z * fn2 + c3.z * fn3;
                    sx4.w = c0.w * fn0 + c1.w * fn1 + c2.w * fn2 + c3.w * fn3;
                    hx4 = __ldcg((const float4*)&g_hx[rd][b * Hd] + (i4 >> 2));
                }
                float4 e = ((const float4*)emb)[(size_t)tok * (Hd / 4) + (i4 >> 2)];
                int p = bb >> 1, off = bb & 1;
                float* dix = (float*)&sm.p1.ix[p][i4] + off;
                float* dhx = (float*)&sm.p1.hx[p][i4] + off;
                float* dfn = (float*)&sm.p1.fin[p][i4] + off;
                dix[0] = e.x + sx4.x; dix[2] = e.y + sx4.y;
                dix[4] = e.z + sx4.z; dix[6] = e.w + sx4.w;
                dhx[0] = hx4.x; dhx[2] = hx4.y; dhx[4] = hx4.z; dhx[6] = hx4.w;
                dfn[0] = hx4.x + sx4.x; dfn[2] = hx4.y + sx4.y;
                dfn[4] = hx4.z + sx4.z; dfn[6] = hx4.w + sx4.w;
            }
            __syncthreads();

            const float* wi0 = W_ih + (size_t)h * Hd;
            const float* wi1 = W_ih + (size_t)(Hd + h) * Hd;
            const float* wi2 = W_ih + (size_t)(2 * Hd + h) * Hd;
            const float* wh0 = W_hh + (size_t)h * Hd;
            const float* wh1 = W_hh + (size_t)(Hd + h) * Hd;
            const float* wh2 = W_hh + (size_t)(2 * Hd + h) * Hd;
            const float* fw  = fc_w + (size_t)(h < Vout ? h : 0) * Hd;

            u64 acc2[6][4], fac2[4];
            #pragma unroll
            for (int g = 0; g < 6; g++)
                #pragma unroll
                for (int j = 0; j < 4; j++) acc2[g][j] = pack2(0.f, 0.f);
            #pragma unroll
            for (int j = 0; j < 4; j++) fac2[j] = pack2(0.f, 0.f);

            const u64* six = (const u64*)sm.p1.ix;
            const u64* shx = (const u64*)sm.p1.hx;
            const u64* sfn = (const u64*)sm.p1.fin;

            for (int i = lane; i < Hd; i += 32) {
                u64 W0 = pack2(wi0[i], wi0[i]);
                u64 W1 = pack2(wi1[i], wi1[i]);
                u64 W2 = pack2(wi2[i], wi2[i]);
                u64 W3 = pack2(wh0[i], wh0[i]);
                u64 W4 = pack2(wh1[i], wh1[i]);
                u64 W5 = pack2(wh2[i], wh2[i]);
                u64 W6 = pack2(fw[i],  fw[i]);
                #pragma unroll
                for (int j = 0; j < 4; j++) {
                    u64 xi = six[j * Hd + i];
                    u64 xh = shx[j * Hd + i];
                    u64 xf = sfn[j * Hd + i];
                    fma2(acc2[0][j], W0, xi);
                    fma2(acc2[1][j], W1, xi);
                    fma2(acc2[2][j], W2, xi);
                    fma2(acc2[3][j], W3, xh);
                    fma2(acc2[4][j], W4, xh);
                    fma2(acc2[5][j], W5, xh);
                    fma2(fac2[j],    W6, xf);
                }
            }

            #pragma unroll
            for (int g = 0; g < 6; g++)
                #pragma unroll
                for (int j = 0; j < 4; j++) acc2[g][j] = warp_sum2(acc2[g][j]);
            #pragma unroll
            for (int j = 0; j < 4; j++) fac2[j] = warp_sum2(fac2[j]);

            float accs[6][8], facs[8];
            #pragma unroll
            for (int g = 0; g < 6; g++)
                #pragma unroll
                for (int j = 0; j < 4; j++)
                    unpack2(acc2[g][j], accs[g][2 * j], accs[g][2 * j + 1]);
            #pragma unroll
            for (int j = 0; j < 4; j++)
                unpack2(fac2[j], facs[2 * j], facs[2 * j + 1]);

            if (lane < 8) {
                int bb = lane, b = b0 + bb;
                float gr = accs[0][bb] + b_ih[h] + accs[3][bb] + b_hh[h];
                float gz = accs[1][bb] + b_ih[Hd + h] + accs[4][bb] + b_hh[Hd + h];
                float r = 1.0f / (1.0f + expf(-gr));
                float z = 1.0f / (1.0f + expf(-gz));
                float n = tanhf(accs[2][bb] + b_ih[2 * Hd + h] +
                                r * (accs[5][bb] + b_hh[2 * Hd + h]));
                float2 hv = sm.p1.hx[bb >> 1][h];
                float hp = (bb & 1) ? hv.y : hv.x;
                g_hx[wr][b * Hd + h] = (1.0f - z) * n + z * hp;
                if (t > 0 && h < Vout)
                    out[(size_t)b * Lsteps * Vout + (size_t)(t - 1) * Vout + h] =
                        facs[bb] + fc_b[h];
            }
        }
        BAR_ARRIVE();

        // ===== overlap region: p23 prep that does NOT depend on new hx ======
        const int b23  = b0 + (lblk >> 2);
        const int tile = lblk & 3;
        const int T0   = tile * 100;
        const int tw = w & 7, thalf = w >> 3;
        const int h0 = tw * 64 + lane * 2;

        if (tid < 114) {   // safe: BAR_ARRIVE's syncthreads ended all p1 reads
            int j = T0 - 7 + tid;
            float vv = 0.0f;
            if (t > 0 && j >= 0 && j < Tenc) {
                float f[4];
                norm_factors(b23, t - 1, f);
                int k = j / 100;
                vv = __ldcg(&aligns[(size_t)b23 * Lsteps * Tenc +
                                    (size_t)(t - 1) * Tenc + j]) * f[k];
            }
            sm.p23.win[tid] = vv;
        }

        u64 cwp0[7], cwp1[7];
        float cw14_0, cw14_1;
        {
            const float* c0p = conv_w + h0 * KS;
            const float* c1p = conv_w + (h0 + 1) * KS;
            #pragma unroll
            for (int m = 0; m < 7; m++) {
                cwp0[m] = pack2(c0p[2 * m], c0p[2 * m + 1]);
                cwp1[m] = pack2(c1p[2 * m], c1p[2 * m + 1]);
            }
            cw14_0 = c0p[14]; cw14_1 = c1p[14];
        }
        float cb0 = conv_b[h0],  cb1 = conv_b[h0 + 1];
        float aw0 = attn_w[h0],  aw1 = attn_w[h0 + 1];

        BAR_WAIT();

        // ===== phase 2+3 (flash): scores -> local softmax -> partial ctx ====
        {
            float2 hx2 = __ldcg((const float2*)&g_hx[wr][b23 * Hd + h0]);

            const float2* xb2 = (const float2*)(x + (size_t)b23 * Tenc * Hd) + (h0 >> 1);
            const int tbase = thalf * 50;

            if (t > 0) {
                #pragma unroll 1
                for (int tc = 0; tc < 5; tc++) {
                    int tl0 = tbase + tc * 10;
                    float2 xv[10];
                    #pragma unroll
                    for (int i = 0; i < 10; i++)
                        xv[i] = xb2[(size_t)(T0 + tl0 + i) * (Hd / 2)];
                    float wvr[24];
                    #pragma unroll
                    for (int j = 0; j < 24; j++) wvr[j] = sm.p23.win[tl0 + j];

                    float sv[10];
                    {   // even i
                        u64 Pe[11];
                        #pragma unroll
                        for (int m = 0; m < 11; m++)
                            Pe[m] = pack2(wvr[2 * m], wvr[2 * m + 1]);
                        #pragma unroll
                        for (int i = 0; i < 10; i += 2) {
                            int j = i >> 1;
                            u64 a0 = pack2(cb0, 0.0f), a1 = pack2(cb1, 0.0f);
                            #pragma unroll
                            for (int m = 0; m < 7; m++) {
                                fma2(a0, cwp0[m], Pe[j + m]);
                                fma2(a1, cwp1[m], Pe[j + m]);
                            }
                            float l0, hh0, l1, hh1;
                            unpack2(a0, l0, hh0); unpack2(a1, l1, hh1);
                            float conv0 = l0 + hh0 + cw14_0 * wvr[i + 14];
                            float conv1 = l1 + hh1 + cw14_1 * wvr[i + 14];
                            float p0 = xv[i].x + hx2.x + conv0;
                            float p1 = xv[i].y + hx2.y + conv1;
                            sv[i] = fmaxf(p0, 0.0f) * aw0 + fmaxf(p1, 0.0f) * aw1;
                        }
                    }
                    {   // odd i
                        u64 Po[11];
                        #pragma unroll
                        for (int m = 0; m < 11; m++)
                            Po[m] = pack2(wvr[2 * m + 1], wvr[2 * m + 2]);
                        #pragma unroll
                        for (int i = 1; i < 10; i += 2) {
                            int j = (i - 1) >> 1;
                            u64 a0 = pack2(cb0, 0.0f), a1 = pack2(cb1, 0.0f);
                            #pragma unroll
                            for (int m = 0; m < 7; m++) {
                                fma2(a0, cwp0[m], Po[j + m]);
                                fma2(a1, cwp1[m], Po[j + m]);
                            }
                            float l0, hh0, l1, hh1;
                            unpack2(a0, l0, hh0); unpack2(a1, l1, hh1);
                            float conv0 = l0 + hh0 + cw14_0 * wvr[i + 14];
                            float conv1 = l1 + hh1 + cw14_1 * wvr[i + 14];
                            float p0 = xv[i].x + hx2.x + conv0;
                            float p1 = xv[i].y + hx2.y + conv1;
                            sv[i] = fmaxf(p0, 0.0f) * aw0 + fmaxf(p1, 0.0f) * aw1;
                        }
                    }
                    // packed t-pair reductions: 5 warp_sum2 instead of 10 warp_sum
                    #pragma unroll
                    for (int j = 0; j < 5; j++) {
                        u64 pr = warp_sum2(pack2(sv[2 * j], sv[2 * j + 1]));
                        if (lane == 0) {
                            float a, bb2; unpack2(pr, a, bb2);
                            *(float2*)&sm.p23.part[tw][tl0 + 2 * j] =
                                make_float2(a, bb2);
                        }
                    }
                }
            } else {
                #pragma unroll 1
                for (int tc = 0; tc < 5; tc++) {
                    int tl0 = tbase + tc * 10;
                    float2 xv[10];
                    #pragma unroll
                    for (int i = 0; i < 10; i++)
                        xv[i] = xb2[(size_t)(T0 + tl0 + i) * (Hd / 2)];
                    float sv[10];
                    #pragma unroll
                    for (int i = 0; i < 10; i++) {
                        float p0 = xv[i].x + hx2.x;
                        float p1 = xv[i].y + hx2.y;
                        sv[i] = fmaxf(p0, 0.0f) * aw0 + fmaxf(p1, 0.0f) * aw1;
                    }
                    #pragma unroll
                    for (int j = 0; j < 5; j++) {
                        u64 pr = warp_sum2(pack2(sv[2 * j], sv[2 * j + 1]));
                        if (lane == 0) {
                            float a, bb2; unpack2(pr, a, bb2);
                            *(float2*)&sm.p23.part[tw][tl0 + 2 * j] =
                                make_float2(a, bb2);
                        }
                    }
                }
            }
            __syncthreads();

            // scores -> sm.a (padded to 128)
            if (tid < 128) {
                float sc = -1e30f;
                if (tid < 100) {
                    float s = 0.0f;
                    #pragma unroll
                    for (int c2 = 0; c2 < 8; c2++) s += sm.p23.part[c2][tid];
                    sc = s + attn_b[0];
                }
                sm.p23.a[tid] = sc;
            }
            __syncthreads();

            // local softmax over this tile's 100 scores
            float m_loc, s_loc;
            if (tid < 128) {
                float v = sm.p23.a[tid];
                float mm = warp_max(v);
                if (lane == 0) sm.p23.red[w] = mm;
            }
            __syncthreads();
            m_loc = fmaxf(fmaxf(sm.p23.red[0], sm.p23.red[1]),
                          fmaxf(sm.p23.red[2], sm.p23.red[3]));
            if (tid < 128) {
                float e = (tid < 100) ? __expf(sm.p23.a[tid] - m_loc) : 0.0f;
                sm.p23.a[tid] = e;
                float ss = warp_sum(e);
                if (lane == 0) sm.p23.red[8 + w] = ss;
            }
            __syncthreads();
            s_loc = (sm.p23.red[8] + sm.p23.red[9]) +
                    (sm.p23.red[10] + sm.p23.red[11]);

            if (tid == 0) g_norm[tile][b23][t] = make_float2(m_loc, s_loc);
            if (tid < 100)
                aligns[(size_t)b23 * Lsteps * Tenc + (size_t)t * Tenc + T0 + tid] =
                    sm.p23.a[tid];   // UNNORMALIZED e; fixed in epilogue

            // partial (unnormalized) context for this tile
            {
                const float* xb = x + (size_t)b23 * Tenc * Hd + (size_t)T0 * Hd + tid;
                float acc[5];
                #pragma unroll
                for (int j = 0; j < 5; j++) acc[j] = 0.0f;
                #pragma unroll 1
                for (int c = 0; c < 10; c++) {
                    int i0 = c * 10;
                    float xr[10];
                    #pragma unroll
                    for (int i = 0; i < 10; i++)
                        xr[i] = xb[(size_t)(i0 + i) * Hd];
                    #pragma unroll
                    for (int i = 0; i < 10; i++)
                        acc[i % 5] = fmaf(sm.p23.a[i0 + i], xr[i], acc[i % 5]);
                }
                float r = (acc[0] + acc[1]) + (acc[2] + acc[3]) + acc[4];
                g_ctxp[tile][b23 * Hd + tid] = r;
            }
        }
        GRID_BARRIER();
    }

    // ===== epilogue A: normalize aligns in place. block = (b, tile) =========
    {
        int b = b0 + (lblk >> 2);
        int tile = lblk & 3;
        int T0 = tile * 100;
        if (tid < 100) {
            float f[4];
            norm_factors(b, tid, f);
            sm.fix.fac[tid] = f[tile];
        }
        __syncthreads();
        for (int idx = tid; idx < 100 * 100; idx += 512) {
            int tp = idx / 100, j = idx - tp * 100;
            size_t off = (size_t)b * Lsteps * Tenc + (size_t)tp * Tenc + T0 + j;
            aligns[off] *= sm.fix.fac[tp];
        }
    }
    __syncthreads();

    // ===== epilogue B: final fc for step 99 (hx in buffer 0) ================
    {
        const int v = (lblk << 4) + w;

        if (tid < 8) {
            float f[4];
            norm_factors(b0 + tid, Lsteps - 1, f);
            sm.p1.fnorm[tid][0] = f[0]; sm.p1.fnorm[tid][1] = f[1];
            sm.p1.fnorm[tid][2] = f[2]; sm.p1.fnorm[tid][3] = f[3];
        }
        __syncthreads();

        for (int idx = tid; idx < 8 * Hd; idx += 512) {
            int bb = idx >> 9, i = idx & 511;
            int b = b0 + bb;
            float fn0 = sm.p1.fnorm[bb][0], fn1 = sm.p1.fnorm[bb][1];
            float fn2 = sm.p1.fnorm[bb][2], fn3 = sm.p1.fnorm[bb][3];
            float sxv = __ldcg(&g_ctxp[0][b * Hd + i]) * fn0 +
                        __ldcg(&g_ctxp[1][b * Hd + i]) * fn1 +
                        __ldcg(&g_ctxp[2][b * Hd + i]) * fn2 +
                        __ldcg(&g_ctxp[3][b * Hd + i]) * fn3;
            sm.pf.in[bb][i] = __ldcg(&g_hx[0][b * Hd + i]) + sxv;
        }
        __syncthreads();

        if (v < Vout) {
            const float* fw = fc_w + (size_t)v * Hd;
            float fac[8];
            #pragma unroll
            for (int bb = 0; bb < 8; bb++) fac[bb] = 0.0f;
            for (int i = lane; i < Hd; i += 32) {
                float wv = fw[i];
                #pragma unroll
                for (int bb = 0; bb < 8; bb++)
                    fac[bb] = fmaf(wv, sm.pf.in[bb][i], fac[bb]);
            }
            #pragma unroll
            for (int bb = 0; bb < 8; bb++) fac[bb] = warp_sum(fac[bb]);
            if (lane < 8) {
                int b = b0 + lane;
                out[(size_t)b * Lsteps * Vout + (size_t)(Lsteps - 1) * Vout + v] =
                    fac[lane] + fc_b[v];
            }
        }
    }
    #undef BAR_ARRIVE
    #undef BAR_WAIT
    #undef GRID_BARRIER
}

// ---------------- launch ------------------------------------------------------
extern "C" void kernel_launch(void* const* d_in, const int* in_sizes, int n_in,
                              void* d_out, int out_size)
{
    const float* x      = (const float*)d_in[0];
    const int*   y      = (const int*)  d_in[1];
    const float* emb    = (const float*)d_in[2];
    const float* W_ih   = (const float*)d_in[3];
    const float* W_hh   = (const float*)d_in[4];
    const float* b_ih   = (const float*)d_in[5];
    const float* b_hh   = (const float*)d_in[6];
    const float* conv_w = (const float*)d_in[7];
    const float* conv_b = (const float*)d_in[8];
    const float* attn_w = (const float*)d_in[9];
    const float* attn_b = (const float*)d_in[10];
    const float* fc_w   = (const float*)d_in[11];
    const float* fc_b   = (const float*)d_in[12];

    float* out    = (float*)d_out;
    float* aligns = out + (size_t)Bsz * Lsteps * Vout;

    static const int smem_sz = (int)sizeof(SmemT);
    cudaFuncSetAttribute(seq2seq_persist,
                         cudaFuncAttributeMaxDynamicSharedMemorySize, smem_sz);

    bar_init<<<1, 1>>>();
    seq2seq_persist<<<NBLK, 512, smem_sz>>>(x, y, emb, W_ih, W_hh, b_ih, b_hh,
                                            conv_w, conv_b, attn_w, attn_b,
                                            fc_w, fc_b, out, aligns);
}

// round 16
// speedup vs baseline: 1.4086x; 1.0182x over previous
#include <cuda_runtime.h>

#define Bsz 32
#define Tenc 400
#define Hd 512
#define Lsteps 100
#define Vout 511
#define KS 15
#define NBLK 128
#define GBLK 32    // blocks per group; group g owns batch octet g

// ---------------- persistent state ------------------------------------------
__device__ float g_hx[2][Bsz * Hd];
__device__ float g_ctxp[4][Bsz * Hd];     // per-tile UNNORMALIZED partial ctx
__device__ float2 g_norm[4][Bsz][Lsteps]; // per-(tile,b,t): (m_loc, s_loc)
__device__ unsigned g_bars[4];            // per-group barrier counters

__device__ __forceinline__ float warp_sum(float v) {
    #pragma unroll
    for (int o = 16; o; o >>= 1) v += __shfl_xor_sync(0xffffffffu, v, o);
    return v;
}
__device__ __forceinline__ float warp_max(float v) {
    #pragma unroll
    for (int o = 16; o; o >>= 1) v = fmaxf(v, __shfl_xor_sync(0xffffffffu, v, o));
    return v;
}

// ---- f32x2 packed math ------------------------------------------------------
typedef unsigned long long u64;
__device__ __forceinline__ u64 pack2(float lo, float hi) {
    u64 r;
    asm("mov.b64 %0, {%1, %2};" : "=l"(r) : "f"(lo), "f"(hi));
    return r;
}
__device__ __forceinline__ void unpack2(u64 v, float& lo, float& hi) {
    asm("mov.b64 {%0, %1}, %2;" : "=f"(lo), "=f"(hi) : "l"(v));
}
__device__ __forceinline__ void fma2(u64& d, u64 a, u64 b) {
    asm("fma.rn.f32x2 %0, %1, %2, %0;" : "+l"(d) : "l"(a), "l"(b));
}
__device__ __forceinline__ void add2(u64& d, u64 a) {
    asm("add.rn.f32x2 %0, %0, %1;" : "+l"(d) : "l"(a));
}
// packed butterfly reduction: elementwise lane-sum of the f32x2 pair
__device__ __forceinline__ u64 warp_sum2(u64 v) {
    #pragma unroll
    for (int o = 16; o; o >>= 1) {
        u64 s = __shfl_xor_sync(0xffffffffu, v, o);
        asm("add.rn.f32x2 %0, %0, %1;" : "+l"(v) : "l"(s));
    }
    return v;
}

// exact flash renorm factors for (b, tstep): f[k] = exp(m_k - M) / S
__device__ __forceinline__ void norm_factors(int b, int tstep, float f[4]) {
    float2 n0 = __ldcg(&g_norm[0][b][tstep]);
    float2 n1 = __ldcg(&g_norm[1][b][tstep]);
    float2 n2 = __ldcg(&g_norm[2][b][tstep]);
    float2 n3 = __ldcg(&g_norm[3][b][tstep]);
    float M = fmaxf(fmaxf(n0.x, n1.x), fmaxf(n2.x, n3.x));
    float e0 = __expf(n0.x - M), e1 = __expf(n1.x - M);
    float e2 = __expf(n2.x - M), e3 = __expf(n3.x - M);
    float S = n0.y * e0 + n1.y * e1 + n2.y * e2 + n3.y * e3;
    float inv = 1.0f / S;
    f[0] = e0 * inv; f[1] = e1 * inv; f[2] = e2 * inv; f[3] = e3 * inv;
}

__global__ void bar_init() {
    g_bars[0] = 0u; g_bars[1] = 0u; g_bars[2] = 0u; g_bars[3] = 0u;
}

struct __align__(16) SmemT {
    union {
        struct { float2 ix[4][Hd]; float2 hx[4][Hd]; float2 fin[4][Hd];
                 float fnorm[8][4]; } p1;                       // 48KB + 128B
        struct { float in[8][Hd]; } pf;                          // 16KB
        struct { float win[128]; float part[8][100]; float a[128];
                 float red[16]; float2 ctxbuf[256]; } p23;
        struct { float fac[128]; } fix;
    };
};
// NOTE: p23.win (offset 0..512B) overlays p1.ix; win is written ONLY after
// BAR_ARRIVE's __syncthreads (all p1 smem reads complete), read after BAR_WAIT.

__global__ void __launch_bounds__(512, 1) seq2seq_persist(
    const float* __restrict__ x, const int* __restrict__ y,
    const float* __restrict__ emb,
    const float* __restrict__ W_ih, const float* __restrict__ W_hh,
    const float* __restrict__ b_ih, const float* __restrict__ b_hh,
    const float* __restrict__ conv_w, const float* __restrict__ conv_b,
    const float* __restrict__ attn_w, const float* __restrict__ attn_b,
    const float* __restrict__ fc_w, const float* __restrict__ fc_b,
    float* __restrict__ out, float* __restrict__ aligns)
{
    extern __shared__ __align__(16) char smraw[];
    SmemT& sm = *reinterpret_cast<SmemT*>(smraw);
    const int bid  = blockIdx.x;
    const int grp  = bid >> 5;          // batch octet 0..3
    const int lblk = bid & 31;          // block within group
    const int b0   = grp << 3;
    const int tid  = threadIdx.x;
    const int w = tid >> 5, lane = tid & 31;

    unsigned barn = 0;

    #define BAR_ARRIVE() do {                                                \
        barn++;                                                              \
        __syncthreads();                                                     \
        if (tid == 0) {                                                      \
            __threadfence();                                                 \
            atomicAdd(&g_bars[grp], 1u);                                     \
        }                                                                    \
    } while (0)
    #define BAR_WAIT() do {                                                  \
        if (tid == 0) {                                                      \
            unsigned target = barn * GBLK;                                   \
            while ((int)(*((volatile unsigned*)&g_bars[grp]) - target) < 0)  \
                __nanosleep(32);                                             \
        }                                                                    \
        __syncthreads();                                                     \
    } while (0)
    #define GRID_BARRIER() do { BAR_ARRIVE(); BAR_WAIT(); } while (0)

    for (int t = 0; t < Lsteps; t++) {
        const int rd = t & 1, wr = rd ^ 1;

        // ===== phase 1: GRU + fc(t-1). block = (16 h-rows, 8 b); warp=(1h,8b)
        {
            const int h = (lblk << 4) + w;   // GRU output row == fc row

            if (t > 0 && tid < 8) {
                float f[4];
                norm_factors(b0 + tid, t - 1, f);
                sm.p1.fnorm[tid][0] = f[0]; sm.p1.fnorm[tid][1] = f[1];
                sm.p1.fnorm[tid][2] = f[2]; sm.p1.fnorm[tid][3] = f[3];
            }
            __syncthreads();

            for (int idx = tid; idx < 8 * (Hd / 4); idx += 512) {
                int bb = idx >> 7, i4 = (idx & 127) << 2;
                int b = b0 + bb;
                int tok = y[b * 101 + t];
                float4 sx4 = make_float4(0.f, 0.f, 0.f, 0.f);
                float4 hx4 = make_float4(0.f, 0.f, 0.f, 0.f);
                if (t > 0) {
                    float fn0 = sm.p1.fnorm[bb][0], fn1 = sm.p1.fnorm[bb][1];
                    float fn2 = sm.p1.fnorm[bb][2], fn3 = sm.p1.fnorm[bb][3];
                    float4 c0 = __ldcg((const float4*)&g_ctxp[0][b * Hd] + (i4 >> 2));
                    float4 c1 = __ldcg((const float4*)&g_ctxp[1][b * Hd] + (i4 >> 2));
                    float4 c2 = __ldcg((const float4*)&g_ctxp[2][b * Hd] + (i4 >> 2));
                    float4 c3 = __ldcg((const float4*)&g_ctxp[3][b * Hd] + (i4 >> 2));
                    sx4.x = c0.x * fn0 + c1.x * fn1 + c2.x * fn2 + c3.x * fn3;
                    sx4.y = c0.y * fn0 + c1.y * fn1 + c2.y * fn2 + c3.y * fn3;
                    sx4.z = c0.z * fn0 + c1.z * fn1 + c2.z * fn2 + c3.z * fn3;
                    sx4.w = c0.w * fn0 + c1.w * fn1 + c2.w * fn2 + c3.w * fn3;
                    hx4 = __ldcg((const float4*)&g_hx[rd][b * Hd] + (i4 >> 2));
                }
                float4 e = ((const float4*)emb)[(size_t)tok * (Hd / 4) + (i4 >> 2)];
                int p = bb >> 1, off = bb & 1;
                float* dix = (float*)&sm.p1.ix[p][i4] + off;
                float* dhx = (float*)&sm.p1.hx[p][i4] + off;
                float* dfn = (float*)&sm.p1.fin[p][i4] + off;
                dix[0] = e.x + sx4.x; dix[2] = e.y + sx4.y;
                dix[4] = e.z + sx4.z; dix[6] = e.w + sx4.w;
                dhx[0] = hx4.x; dhx[2] = hx4.y; dhx[4] = hx4.z; dhx[6] = hx4.w;
                dfn[0] = hx4.x + sx4.x; dfn[2] = hx4.y + sx4.y;
                dfn[4] = hx4.z + sx4.z; dfn[6] = hx4.w + sx4.w;
            }
            __syncthreads();

            const float* wi0 = W_ih + (size_t)h * Hd;
            const float* wi1 = W_ih + (size_t)(Hd + h) * Hd;
            const float* wi2 = W_ih + (size_t)(2 * Hd + h) * Hd;
            const float* wh0 = W_hh + (size_t)h * Hd;
            const float* wh1 = W_hh + (size_t)(Hd + h) * Hd;
            const float* wh2 = W_hh + (size_t)(2 * Hd + h) * Hd;
            const float* fw  = fc_w + (size_t)(h < Vout ? h : 0) * Hd;

            u64 acc2[6][4], fac2[4];
            #pragma unroll
            for (int g = 0; g < 6; g++)
                #pragma unroll
                for (int j = 0; j < 4; j++) acc2[g][j] = pack2(0.f, 0.f);
            #pragma unroll
            for (int j = 0; j < 4; j++) fac2[j] = pack2(0.f, 0.f);

            const u64* six = (const u64*)sm.p1.ix;
            const u64* shx = (const u64*)sm.p1.hx;
            const u64* sfn = (const u64*)sm.p1.fin;

            for (int i = lane; i < Hd; i += 32) {
                u64 W0 = pack2(wi0[i], wi0[i]);
                u64 W1 = pack2(wi1[i], wi1[i]);
                u64 W2 = pack2(wi2[i], wi2[i]);
                u64 W3 = pack2(wh0[i], wh0[i]);
                u64 W4 = pack2(wh1[i], wh1[i]);
                u64 W5 = pack2(wh2[i], wh2[i]);
                u64 W6 = pack2(fw[i],  fw[i]);
                #pragma unroll
                for (int j = 0; j < 4; j++) {
                    u64 xi = six[j * Hd + i];
                    u64 xh = shx[j * Hd + i];
                    u64 xf = sfn[j * Hd + i];
                    fma2(acc2[0][j], W0, xi);
                    fma2(acc2[1][j], W1, xi);
                    fma2(acc2[2][j], W2, xi);
                    fma2(acc2[3][j], W3, xh);
                    fma2(acc2[4][j], W4, xh);
                    fma2(acc2[5][j], W5, xh);
                    fma2(fac2[j],    W6, xf);
                }
            }

            #pragma unroll
            for (int g = 0; g < 6; g++)
                #pragma unroll
                for (int j = 0; j < 4; j++) acc2[g][j] = warp_sum2(acc2[g][j]);
            #pragma unroll
            for (int j = 0; j < 4; j++) fac2[j] = warp_sum2(fac2[j]);

            float accs[6][8], facs[8];
            #pragma unroll
            for (int g = 0; g < 6; g++)
                #pragma unroll
                for (int j = 0; j < 4; j++)
                    unpack2(acc2[g][j], accs[g][2 * j], accs[g][2 * j + 1]);
            #pragma unroll
            for (int j = 0; j < 4; j++)
                unpack2(fac2[j], facs[2 * j], facs[2 * j + 1]);

            if (lane < 8) {
                int bb = lane, b = b0 + bb;
                float gr = accs[0][bb] + b_ih[h] + accs[3][bb] + b_hh[h];
                float gz = accs[1][bb] + b_ih[Hd + h] + accs[4][bb] + b_hh[Hd + h];
                float r = 1.0f / (1.0f + expf(-gr));
                float z = 1.0f / (1.0f + expf(-gz));
                float n = tanhf(accs[2][bb] + b_ih[2 * Hd + h] +
                                r * (accs[5][bb] + b_hh[2 * Hd + h]));
                float2 hv = sm.p1.hx[bb >> 1][h];
                float hp = (bb & 1) ? hv.y : hv.x;
                g_hx[wr][b * Hd + h] = (1.0f - z) * n + z * hp;
                if (t > 0 && h < Vout)
                    out[(size_t)b * Lsteps * Vout + (size_t)(t - 1) * Vout + h] =
                        facs[bb] + fc_b[h];
            }
        }
        BAR_ARRIVE();

        // ===== overlap region: p23 prep that does NOT depend on new hx ======
        const int b23  = b0 + (lblk >> 2);
        const int tile = lblk & 3;
        const int T0   = tile * 100;
        const int tw = w & 7, thalf = w >> 3;
        const int h0 = tw * 64 + lane * 2;

        if (tid < 114) {   // safe: BAR_ARRIVE's syncthreads ended all p1 reads
            int j = T0 - 7 + tid;
            float vv = 0.0f;
            if (t > 0 && j >= 0 && j < Tenc) {
                float f[4];
                norm_factors(b23, t - 1, f);
                int k = j / 100;
                vv = __ldcg(&aligns[(size_t)b23 * Lsteps * Tenc +
                                    (size_t)(t - 1) * Tenc + j]) * f[k];
            }
            sm.p23.win[tid] = vv;
        }

        u64 cwp0[7], cwp1[7];
        float cw14_0, cw14_1;
        {
            const float* c0p = conv_w + h0 * KS;
            const float* c1p = conv_w + (h0 + 1) * KS;
            #pragma unroll
            for (int m = 0; m < 7; m++) {
                cwp0[m] = pack2(c0p[2 * m], c0p[2 * m + 1]);
                cwp1[m] = pack2(c1p[2 * m], c1p[2 * m + 1]);
            }
            cw14_0 = c0p[14]; cw14_1 = c1p[14];
        }
        float cb0 = conv_b[h0],  cb1 = conv_b[h0 + 1];
        float aw0 = attn_w[h0],  aw1 = attn_w[h0 + 1];

        BAR_WAIT();

        // ===== phase 2+3 (flash): scores -> local softmax -> partial ctx ====
        {
            float2 hx2 = __ldcg((const float2*)&g_hx[wr][b23 * Hd + h0]);

            const float2* xb2 = (const float2*)(x + (size_t)b23 * Tenc * Hd) + (h0 >> 1);
            const int tbase = thalf * 50;

            if (t > 0) {
                #pragma unroll 1
                for (int tc = 0; tc < 5; tc++) {
                    int tl0 = tbase + tc * 10;
                    float2 xv[10];
                    #pragma unroll
                    for (int i = 0; i < 10; i++)
                        xv[i] = xb2[(size_t)(T0 + tl0 + i) * (Hd / 2)];
                    float wvr[24];
                    #pragma unroll
                    for (int j = 0; j < 24; j++) wvr[j] = sm.p23.win[tl0 + j];

                    float sv[10];
                    {   // even i
                        u64 Pe[11];
                        #pragma unroll
                        for (int m = 0; m < 11; m++)
                            Pe[m] = pack2(wvr[2 * m], wvr[2 * m + 1]);
                        #pragma unroll
                        for (int i = 0; i < 10; i += 2) {
                            int j = i >> 1;
                            u64 a0 = pack2(cb0, 0.0f), a1 = pack2(cb1, 0.0f);
                            #pragma unroll
                            for (int m = 0; m < 7; m++) {
                                fma2(a0, cwp0[m], Pe[j + m]);
                                fma2(a1, cwp1[m], Pe[j + m]);
                            }
                            float l0, hh0, l1, hh1;
                            unpack2(a0, l0, hh0); unpack2(a1, l1, hh1);
                            float conv0 = l0 + hh0 + cw14_0 * wvr[i + 14];
                            float conv1 = l1 + hh1 + cw14_1 * wvr[i + 14];
                            float p0 = xv[i].x + hx2.x + conv0;
                            float p1 = xv[i].y + hx2.y + conv1;
                            sv[i] = fmaxf(p0, 0.0f) * aw0 + fmaxf(p1, 0.0f) * aw1;
                        }
                    }
                    {   // odd i
                        u64 Po[11];
                        #pragma unroll
                        for (int m = 0; m < 11; m++)
                            Po[m] = pack2(wvr[2 * m + 1], wvr[2 * m + 2]);
                        #pragma unroll
                        for (int i = 1; i < 10; i += 2) {
                            int j = (i - 1) >> 1;
                            u64 a0 = pack2(cb0, 0.0f), a1 = pack2(cb1, 0.0f);
                            #pragma unroll
                            for (int m = 0; m < 7; m++) {
                                fma2(a0, cwp0[m], Po[j + m]);
                                fma2(a1, cwp1[m], Po[j + m]);
                            }
                            float l0, hh0, l1, hh1;
                            unpack2(a0, l0, hh0); unpack2(a1, l1, hh1);
                            float conv0 = l0 + hh0 + cw14_0 * wvr[i + 14];
                            float conv1 = l1 + hh1 + cw14_1 * wvr[i + 14];
                            float p0 = xv[i].x + hx2.x + conv0;
                            float p1 = xv[i].y + hx2.y + conv1;
                            sv[i] = fmaxf(p0, 0.0f) * aw0 + fmaxf(p1, 0.0f) * aw1;
                        }
                    }
                    #pragma unroll
                    for (int j = 0; j < 5; j++) {
                        u64 pr = warp_sum2(pack2(sv[2 * j], sv[2 * j + 1]));
                        if (lane == 0) {
                            float a, bb2; unpack2(pr, a, bb2);
                            *(float2*)&sm.p23.part[tw][tl0 + 2 * j] =
                                make_float2(a, bb2);
                        }
                    }
                }
            } else {
                #pragma unroll 1
                for (int tc = 0; tc < 5; tc++) {
                    int tl0 = tbase + tc * 10;
                    float2 xv[10];
                    #pragma unroll
                    for (int i = 0; i < 10; i++)
                        xv[i] = xb2[(size_t)(T0 + tl0 + i) * (Hd / 2)];
                    float sv[10];
                    #pragma unroll
                    for (int i = 0; i < 10; i++) {
                        float p0 = xv[i].x + hx2.x;
                        float p1 = xv[i].y + hx2.y;
                        sv[i] = fmaxf(p0, 0.0f) * aw0 + fmaxf(p1, 0.0f) * aw1;
                    }
                    #pragma unroll
                    for (int j = 0; j < 5; j++) {
                        u64 pr = warp_sum2(pack2(sv[2 * j], sv[2 * j + 1]));
                        if (lane == 0) {
                            float a, bb2; unpack2(pr, a, bb2);
                            *(float2*)&sm.p23.part[tw][tl0 + 2 * j] =
                                make_float2(a, bb2);
                        }
                    }
                }
            }
            __syncthreads();

            // scores -> sm.a (padded to 128)
            if (tid < 128) {
                float sc = -1e30f;
                if (tid < 100) {
                    float s = 0.0f;
                    #pragma unroll
                    for (int c2 = 0; c2 < 8; c2++) s += sm.p23.part[c2][tid];
                    sc = s + attn_b[0];
                }
                sm.p23.a[tid] = sc;
            }
            __syncthreads();

            // local softmax over this tile's 100 scores
            float m_loc, s_loc;
            if (tid < 128) {
                float v = sm.p23.a[tid];
                float mm = warp_max(v);
                if (lane == 0) sm.p23.red[w] = mm;
            }
            __syncthreads();
            m_loc = fmaxf(fmaxf(sm.p23.red[0], sm.p23.red[1]),
                          fmaxf(sm.p23.red[2], sm.p23.red[3]));
            if (tid < 128) {
                float e = (tid < 100) ? __expf(sm.p23.a[tid] - m_loc) : 0.0f;
                sm.p23.a[tid] = e;
                float ss = warp_sum(e);
                if (lane == 0) sm.p23.red[8 + w] = ss;
            }
            __syncthreads();
            s_loc = (sm.p23.red[8] + sm.p23.red[9]) +
                    (sm.p23.red[10] + sm.p23.red[11]);

            if (tid == 0) g_norm[tile][b23][t] = make_float2(m_loc, s_loc);
            if (tid < 100)
                aligns[(size_t)b23 * Lsteps * Tenc + (size_t)t * Tenc + T0 + tid] =
                    sm.p23.a[tid];   // UNNORMALIZED e; fixed in epilogue

            // partial (unnormalized) context: thread = (h-pair, t-half)
            {
                int hp  = tid & 255;       // h-pair: h = 2*hp, 2*hp+1
                int seg = tid >> 8;        // t-segment 0/1 (50 t each)
                const float2* xbc =
                    (const float2*)(x + (size_t)b23 * Tenc * Hd) + hp;
                int ts = T0 + seg * 50;
                int as = seg * 50;
                u64 acc[5];
                #pragma unroll
                for (int j = 0; j < 5; j++) acc[j] = pack2(0.f, 0.f);
                #pragma unroll 1
                for (int c = 0; c < 5; c++) {
                    int i0 = c * 10;
                    float2 xr[10];
                    #pragma unroll
                    for (int i = 0; i < 10; i++)
                        xr[i] = xbc[(size_t)(ts + i0 + i) * (Hd / 2)];
                    #pragma unroll
                    for (int i = 0; i < 10; i++) {
                        float a = sm.p23.a[as + i0 + i];
                        fma2(acc[i % 5], pack2(a, a), pack2(xr[i].x, xr[i].y));
                    }
                }
                add2(acc[0], acc[1]); add2(acc[2], acc[3]);
                add2(acc[0], acc[2]); add2(acc[0], acc[4]);
                if (seg == 1) {
                    float lo, hi; unpack2(acc[0], lo, hi);
                    sm.p23.ctxbuf[hp] = make_float2(lo, hi);
                }
                __syncthreads();
                if (seg == 0) {
                    float lo, hi; unpack2(acc[0], lo, hi);
                    float2 o = sm.p23.ctxbuf[hp];
                    ((float2*)&g_ctxp[tile][b23 * Hd])[hp] =
                        make_float2(lo + o.x, hi + o.y);
                }
            }
        }
        GRID_BARRIER();
    }

    // ===== epilogue A: normalize aligns in place. block = (b, tile) =========
    {
        int b = b0 + (lblk >> 2);
        int tile = lblk & 3;
        int T0 = tile * 100;
        if (tid < 100) {
            float f[4];
            norm_factors(b, tid, f);
            sm.fix.fac[tid] = f[tile];
        }
        __syncthreads();
        for (int idx = tid; idx < 100 * 100; idx += 512) {
            int tp = idx / 100, j = idx - tp * 100;
            size_t off = (size_t)b * Lsteps * Tenc + (size_t)tp * Tenc + T0 + j;
            aligns[off] *= sm.fix.fac[tp];
        }
    }
    __syncthreads();

    // ===== epilogue B: final fc for step 99 (hx in buffer 0) ================
    {
        const int v = (lblk << 4) + w;

        if (tid < 8) {
            float f[4];
            norm_factors(b0 + tid, Lsteps - 1, f);
            sm.p1.fnorm[tid][0] = f[0]; sm.p1.fnorm[tid][1] = f[1];
            sm.p1.fnorm[tid][2] = f[2]; sm.p1.fnorm[tid][3] = f[3];
        }
        __syncthreads();

        for (int idx = tid; idx < 8 * Hd; idx += 512) {
            int bb = idx >> 9, i = idx & 511;
            int b = b0 + bb;
            float fn0 = sm.p1.fnorm[bb][0], fn1 = sm.p1.fnorm[bb][1];
            float fn2 = sm.p1.fnorm[bb][2], fn3 = sm.p1.fnorm[bb][3];
            float sxv = __ldcg(&g_ctxp[0][b * Hd + i]) * fn0 +
                        __ldcg(&g_ctxp[1][b * Hd + i]) * fn1 +
                        __ldcg(&g_ctxp[2][b * Hd + i]) * fn2 +
                        __ldcg(&g_ctxp[3][b * Hd + i]) * fn3;
            sm.pf.in[bb][i] = __ldcg(&g_hx[0][b * Hd + i]) + sxv;
        }
        __syncthreads();

        if (v < Vout) {
            const float* fw = fc_w + (size_t)v * Hd;
            float fac[8];
            #pragma unroll
            for (int bb = 0; bb < 8; bb++) fac[bb] = 0.0f;
            for (int i = lane; i < Hd; i += 32) {
                float wv = fw[i];
                #pragma unroll
                for (int bb = 0; bb < 8; bb++)
                    fac[bb] = fmaf(wv, sm.pf.in[bb][i], fac[bb]);
            }
            #pragma unroll
            for (int bb = 0; bb < 8; bb++) fac[bb] = warp_sum(fac[bb]);
            if (lane < 8) {
                int b = b0 + lane;
                out[(size_t)b * Lsteps * Vout + (size_t)(Lsteps - 1) * Vout + v] =
                    fac[lane] + fc_b[v];
            }
        }
    }
    #undef BAR_ARRIVE
    #undef BAR_WAIT
    #undef GRID_BARRIER
}

// ---------------- launch ------------------------------------------------------
extern "C" void kernel_launch(void* const* d_in, const int* in_sizes, int n_in,
                              void* d_out, int out_size)
{
    const float* x      = (const float*)d_in[0];
    const int*   y      = (const int*)  d_in[1];
    const float* emb    = (const float*)d_in[2];
    const float* W_ih   = (const float*)d_in[3];
    const float* W_hh   = (const float*)d_in[4];
    const float* b_ih   = (const float*)d_in[5];
    const float* b_hh   = (const float*)d_in[6];
    const float* conv_w = (const float*)d_in[7];
    const float* conv_b = (const float*)d_in[8];
    const float* attn_w = (const float*)d_in[9];
    const float* attn_b = (const float*)d_in[10];
    const float* fc_w   = (const float*)d_in[11];
    const float* fc_b   = (const float*)d_in[12];

    float* out    = (float*)d_out;
    float* aligns = out + (size_t)Bsz * Lsteps * Vout;

    static const int smem_sz = (int)sizeof(SmemT);
    cudaFuncSetAttribute(seq2seq_persist,
                         cudaFuncAttributeMaxDynamicSharedMemorySize, smem_sz);

    bar_init<<<1, 1>>>();
    seq2seq_persist<<<NBLK, 512, smem_sz>>>(x, y, emb, W_ih, W_hh, b_ih, b_hh,
                                            conv_w, conv_b, attn_w, attn_b,
                                            fc_w, fc_b, out, aligns);
}